// round 1
// baseline (speedup 1.0000x reference)
#include <cuda_runtime.h>

#define NN 12288
#define EE 393216
#define IND 256
#define HH 64

// ---------------- scratch (static device globals; no allocation) -------------
__device__ int   g_deg[NN];
__device__ float g_dinv[NN];
__device__ int   g_rowptr[NN + 1];
__device__ int   g_fill[NN];
__device__ int   g_col[EE];
__device__ float g_wgt[EE];
__device__ float g_u[NN];
__device__ float g_Au[NN];
__device__ float gB0[NN * HH];
__device__ float gB1[NN * HH];
__device__ float gB2[NN * HH];
__device__ float gB3[NN * HH];
__device__ float gB4[NN * HH];
__device__ float gB5[NN * HH];
__device__ float gB6[NN * HH];
__device__ float gB7[NN * HH];

// ---------------- graph preprocessing ----------------------------------------
__global__ void k_zero_deg() {
    int i = blockIdx.x * blockDim.x + threadIdx.x;
    if (i < NN) g_deg[i] = 0;
}

__global__ void k_count(const int* __restrict__ ei) {
    int e = blockIdx.x * blockDim.x + threadIdx.x;
    if (e < EE) atomicAdd(&g_deg[ei[EE + e]], 1);
}

__global__ void k_dinv() {
    int i = blockIdx.x * blockDim.x + threadIdx.x;
    if (i < NN) g_dinv[i] = rsqrtf((float)g_deg[i] + 1.0f);  // +1 self loop
}

// single-block exclusive scan of g_deg -> g_rowptr ; also seeds g_fill
__global__ void k_scan() {
    __shared__ int part[1024];
    int t = threadIdx.x;
    int base = t * 12;
    int s = 0;
#pragma unroll
    for (int i = 0; i < 12; i++) s += g_deg[base + i];
    part[t] = s;
    __syncthreads();
    if (t == 0) {
        int acc = 0;
        for (int i = 0; i < 1024; i++) { int v = part[i]; part[i] = acc; acc += v; }
        g_rowptr[NN] = acc;
    }
    __syncthreads();
    int acc = part[t];
    for (int i = 0; i < 12; i++) {
        g_rowptr[base + i] = acc;
        g_fill[base + i] = acc;
        acc += g_deg[base + i];
    }
}

__global__ void k_fill(const int* __restrict__ ei) {
    int e = blockIdx.x * blockDim.x + threadIdx.x;
    if (e >= EE) return;
    int s = ei[e], d = ei[EE + e];
    int p = atomicAdd(&g_fill[d], 1);
    g_col[p] = s;
    g_wgt[p] = g_dinv[s] * g_dinv[d];
}

// ---------------- counterfactual rank-1 helpers -------------------------------
__global__ void k_u(const float* __restrict__ x) {
    int i = blockIdx.x * blockDim.x + threadIdx.x;
    if (i < NN) g_u[i] = 1.0f - 2.0f * x[(size_t)i * IND];
}

__global__ void k_agg_scalar() {
    int i = blockIdx.x * blockDim.x + threadIdx.x;
    if (i >= NN) return;
    float di = g_dinv[i];
    float acc = di * di * g_u[i];
    int e = g_rowptr[i + 1];
    for (int p = g_rowptr[i]; p < e; p++) acc += g_wgt[p] * g_u[g_col[p]];
    g_Au[i] = acc;
}

// a1 (gB1) -> h1r=relu(a1) in place ; gB2 = relu(a1 + Au * W1row0)
__global__ void k_rank1relu(const float* __restrict__ W1row0) {
    int i = blockIdx.x, t = threadIdx.x;
    float a = gB1[i * HH + t];
    gB2[i * HH + t] = fmaxf(a + g_Au[i] * W1row0[t], 0.0f);
    gB1[i * HH + t] = fmaxf(a, 0.0f);
}

// ---------------- sparse aggregation: out[i,:] = sum_j A[i,j] in[j, off:off+D]
// one block per row, D = blockDim.x threads (feature-parallel, coalesced gathers)
__global__ void k_agg(const float* __restrict__ in, int ldi, int off,
                      const float* __restrict__ bias, float* __restrict__ outp) {
    int i = blockIdx.x, t = threadIdx.x;
    int D = blockDim.x;
    float di = g_dinv[i];
    float acc = di * di * in[(size_t)i * ldi + off + t];
    int p = g_rowptr[i], e = g_rowptr[i + 1];
    for (; p + 4 <= e; p += 4) {
        int c0 = g_col[p], c1 = g_col[p + 1], c2 = g_col[p + 2], c3 = g_col[p + 3];
        float w0 = g_wgt[p], w1 = g_wgt[p + 1], w2 = g_wgt[p + 2], w3 = g_wgt[p + 3];
        float v0 = in[(size_t)c0 * ldi + off + t];
        float v1 = in[(size_t)c1 * ldi + off + t];
        float v2 = in[(size_t)c2 * ldi + off + t];
        float v3 = in[(size_t)c3 * ldi + off + t];
        acc += w0 * v0 + w1 * v1 + w2 * v2 + w3 * v3;
    }
    for (; p < e; p++) acc += g_wgt[p] * in[(size_t)g_col[p] * ldi + off + t];
    if (bias) acc += bias[t];
    outp[(size_t)i * D + t] = acc;
}

// ---------------- small dense GEMM: out[N x M] = A[N x K] @ W[K x M] (+b)(relu)
template <int K, int M, int R, bool RELU, bool BIAS>
__global__ void k_gemm(const float* __restrict__ A, int lda,
                       const float* __restrict__ W,
                       const float* __restrict__ bias,
                       float* __restrict__ outp, int ldo) {
    __shared__ float sA[R][K];
    int r0 = blockIdx.x * R;
    int tid = threadIdx.x;  // M threads
    for (int idx = tid; idx < R * K; idx += M) {
        int r = idx / K, k = idx % K;
        sA[r][k] = A[(size_t)(r0 + r) * lda + k];
    }
    __syncthreads();
    float acc[R];
#pragma unroll
    for (int r = 0; r < R; r++) acc[r] = BIAS ? bias[tid] : 0.0f;
    for (int k = 0; k < K; k++) {
        float w = __ldg(&W[k * M + tid]);
#pragma unroll
        for (int r = 0; r < R; r++) acc[r] += sA[r][k] * w;
    }
#pragma unroll
    for (int r = 0; r < R; r++) {
        float v = acc[r];
        if (RELU) v = fmaxf(v, 0.0f);
        outp[(size_t)(r0 + r) * ldo + tid] = v;
    }
}

__global__ void k_split(const float* __restrict__ z,
                        float* __restrict__ zs, float* __restrict__ zns) {
    int i = blockIdx.x, t = threadIdx.x;
    float v = z[i * HH + t];
    if (t < 32) zs[i * 32 + t] = v;
    else        zns[i * 32 + (t - 32)] = v;
}

// ---------------- s_ = hs @ hs^T  (symmetric; upper-tri tiles, mirrored write)
__global__ void __launch_bounds__(256) k_sgemm_sym(const float* __restrict__ hs,
                                                   float* __restrict__ outp) {
    int bi = blockIdx.y, bj = blockIdx.x;
    if (bj < bi) return;
    __shared__ float As[32][132];
    __shared__ float Bs[32][132];
    int tid = threadIdx.x;
    int tx = tid & 15, ty = tid >> 4;
    int lrow = tid >> 1;
    int khalf = (tid & 1) * 16;

    float acc[8][8];
#pragma unroll
    for (int i = 0; i < 8; i++)
#pragma unroll
        for (int j = 0; j < 8; j++) acc[i][j] = 0.0f;

    const float* gA = hs + (size_t)(bi * 128 + lrow) * 64 + khalf;
    const float* gB = hs + (size_t)(bj * 128 + lrow) * 64 + khalf;

#pragma unroll
    for (int kt = 0; kt < 2; kt++) {
        float4 a4[4], b4[4];
#pragma unroll
        for (int q = 0; q < 4; q++) {
            a4[q] = *(const float4*)(gA + kt * 32 + q * 4);
            b4[q] = *(const float4*)(gB + kt * 32 + q * 4);
        }
        __syncthreads();
#pragma unroll
        for (int q = 0; q < 4; q++) {
            int k = khalf + q * 4;
            As[k + 0][lrow] = a4[q].x; As[k + 1][lrow] = a4[q].y;
            As[k + 2][lrow] = a4[q].z; As[k + 3][lrow] = a4[q].w;
            Bs[k + 0][lrow] = b4[q].x; Bs[k + 1][lrow] = b4[q].y;
            Bs[k + 2][lrow] = b4[q].z; Bs[k + 3][lrow] = b4[q].w;
        }
        __syncthreads();
#pragma unroll
        for (int k = 0; k < 32; k++) {
            float a[8], b[8];
            *(float4*)&a[0] = *(const float4*)&As[k][ty * 8];
            *(float4*)&a[4] = *(const float4*)&As[k][ty * 8 + 4];
            *(float4*)&b[0] = *(const float4*)&Bs[k][tx * 8];
            *(float4*)&b[4] = *(const float4*)&Bs[k][tx * 8 + 4];
#pragma unroll
            for (int i = 0; i < 8; i++)
#pragma unroll
                for (int j = 0; j < 8; j++) acc[i][j] += a[i] * b[j];
        }
    }

    {
        float* o = outp + (size_t)(bi * 128 + ty * 8) * NN + bj * 128 + tx * 8;
#pragma unroll
        for (int i = 0; i < 8; i++) {
            *(float4*)(o + (size_t)i * NN)     = make_float4(acc[i][0], acc[i][1], acc[i][2], acc[i][3]);
            *(float4*)(o + (size_t)i * NN + 4) = make_float4(acc[i][4], acc[i][5], acc[i][6], acc[i][7]);
        }
    }
    if (bi != bj) {
        float* o = outp + (size_t)(bj * 128 + tx * 8) * NN + bi * 128 + ty * 8;
#pragma unroll
        for (int j = 0; j < 8; j++) {
            *(float4*)(o + (size_t)j * NN)     = make_float4(acc[0][j], acc[1][j], acc[2][j], acc[3][j]);
            *(float4*)(o + (size_t)j * NN + 4) = make_float4(acc[4][j], acc[5][j], acc[6][j], acc[7][j]);
        }
    }
}

// ---------------- host orchestration -----------------------------------------
extern "C" void kernel_launch(void* const* d_in, const int* in_sizes, int n_in,
                              void* d_out, int out_size) {
    const float* x    = (const float*)d_in[0];
    const int*   ei   = (const int*)d_in[1];
    const float* eW1  = (const float*)d_in[2];
    const float* eb1  = (const float*)d_in[3];
    const float* eW2  = (const float*)d_in[4];
    const float* eb2  = (const float*)d_in[5];
    const float* d1W1 = (const float*)d_in[6];
    const float* d1b1 = (const float*)d_in[7];
    const float* d1W2 = (const float*)d_in[8];
    const float* d1b2 = (const float*)d_in[9];
    const float* d2W1 = (const float*)d_in[10];
    const float* d2b1 = (const float*)d_in[11];
    const float* d2W2 = (const float*)d_in[12];
    const float* d2b2 = (const float*)d_in[13];
    const float* sW   = (const float*)d_in[14];
    const float* sb   = (const float*)d_in[15];

    float* out  = (float*)d_out;
    float* o_zs  = out;
    float* o_zns = out + (size_t)NN * 32;
    float* o_x1  = out + (size_t)NN * 64;
    float* o_x2  = o_x1 + (size_t)NN * 256;
    float* o_x3  = o_x2 + (size_t)NN * 256;
    float* o_s   = o_x3 + (size_t)NN * 256;

    float *B0, *B1, *B2, *B3, *B4, *B5, *B6, *B7;
    cudaGetSymbolAddress((void**)&B0, gB0);
    cudaGetSymbolAddress((void**)&B1, gB1);
    cudaGetSymbolAddress((void**)&B2, gB2);
    cudaGetSymbolAddress((void**)&B3, gB3);
    cudaGetSymbolAddress((void**)&B4, gB4);
    cudaGetSymbolAddress((void**)&B5, gB5);
    cudaGetSymbolAddress((void**)&B6, gB6);
    cudaGetSymbolAddress((void**)&B7, gB7);

    // graph preprocessing (CSR + norms), reused by all 8 aggregations
    k_zero_deg<<<(NN + 255) / 256, 256>>>();
    k_count<<<(EE + 255) / 256, 256>>>(ei);
    k_dinv<<<(NN + 255) / 256, 256>>>();
    k_scan<<<1, 1024>>>();
    k_fill<<<(EE + 255) / 256, 256>>>(ei);
    k_u<<<(NN + 255) / 256, 256>>>(x);
    k_agg_scalar<<<(NN + 255) / 256, 256>>>();

    // encoder layer 1: a1 = A@(x@W1) + b1 ; cf path via rank-1 correction
    k_gemm<256, 64, 8, false, false><<<NN / 8, 64>>>(x, IND, eW1, nullptr, B0, 64);
    k_agg<<<NN, 64>>>(B0, 64, 0, eb1, B1);           // B1 = a1
    k_rank1relu<<<NN, 64>>>(eW1);                    // B1 = relu(a1), B2 = relu(a1_cf)

    // encoder layer 2 (both paths): z = A@(h@W2) + b2
    k_gemm<64, 64, 8, false, false><<<NN / 8, 64>>>(B1, 64, eW2, nullptr, B3, 64);
    k_agg<<<NN, 64>>>(B3, 64, 0, eb2, B4);           // B4 = z
    k_gemm<64, 64, 8, false, false><<<NN / 8, 64>>>(B2, 64, eW2, nullptr, B3, 64);
    k_agg<<<NN, 64>>>(B3, 64, 0, eb2, B5);           // B5 = z_cf

    k_split<<<NN, 64>>>(B4, o_zs, o_zns);

    // dec1(z_s):  h = relu((A@z_s)@W1 + b) ; x_s_hat = (A@h)@W2 + b
    k_agg<<<NN, 32>>>(B4, 64, 0, nullptr, B6);
    k_gemm<32, 64, 8, true, true><<<NN / 8, 64>>>(B6, 32, d1W1, d1b1, B7, 64);
    k_agg<<<NN, 64>>>(B7, 64, 0, nullptr, B3);
    k_gemm<64, 256, 8, false, true><<<NN / 8, 256>>>(B3, 64, d1W2, d1b2, o_x1, 256);

    // z_ns path: shared aggregation feeds hs and dec2
    k_agg<<<NN, 32>>>(B4, 64, 32, nullptr, B6);      // B6 = A@z_ns
    k_gemm<32, 64, 8, false, true><<<NN / 8, 64>>>(B6, 32, sW, sb, B0, 64);  // B0 = hs
    k_gemm<32, 64, 8, true, true><<<NN / 8, 64>>>(B6, 32, d2W1, d2b1, B7, 64);
    k_agg<<<NN, 64>>>(B7, 64, 0, nullptr, B3);
    k_gemm<64, 256, 8, false, true><<<NN / 8, 256>>>(B3, 64, d2W2, d2b2, o_x2, 256);

    // dec1(z_s_cf)
    k_agg<<<NN, 32>>>(B5, 64, 0, nullptr, B6);
    k_gemm<32, 64, 8, true, true><<<NN / 8, 64>>>(B6, 32, d1W1, d1b1, B7, 64);
    k_agg<<<NN, 64>>>(B7, 64, 0, nullptr, B3);
    k_gemm<64, 256, 8, false, true><<<NN / 8, 256>>>(B3, 64, d1W2, d1b2, o_x3, 256);

    // s_ = hs @ hs^T (symmetric)
    dim3 grid(NN / 128, NN / 128);
    k_sgemm_sym<<<grid, 256>>>(B0, o_s);
}

// round 2
// speedup vs baseline: 1.2376x; 1.2376x over previous
#include <cuda_runtime.h>
#include <cstdint>

#define NN 12288
#define EE 393216
#define IND 256
#define HH 64

// ---------------- scratch (static device globals; no allocation) -------------
__device__ int   g_deg[NN];
__device__ float g_dinv[NN];
__device__ int   g_rowptr[NN + 1];
__device__ int   g_fill[NN];
__device__ int   g_col[EE];
__device__ float g_wgt[EE];
__device__ float g_u[NN];
__device__ float g_Au[NN];
__device__ float gB0[NN * HH];
__device__ float gB1[NN * HH];
__device__ float gB2[NN * HH];
__device__ float gB3[NN * HH];
__device__ float gB4[NN * HH];
__device__ float gB5[NN * HH];
__device__ float gB6[NN * HH];
__device__ float gB7[NN * HH];

// ---------------- graph preprocessing ----------------------------------------
__global__ void k_zero_deg() {
    int i = blockIdx.x * blockDim.x + threadIdx.x;
    if (i < NN) g_deg[i] = 0;
}

__global__ void k_count(const int* __restrict__ ei) {
    int e = blockIdx.x * blockDim.x + threadIdx.x;
    if (e < EE) atomicAdd(&g_deg[ei[EE + e]], 1);
}

// parallel exclusive scan of g_deg -> g_rowptr/g_fill ; also computes dinv
__global__ void k_scan() {
    __shared__ int wsum[32];
    int t = threadIdx.x;               // 1024 threads
    int base = t * 12;
    int local[12];
    int s = 0;
#pragma unroll
    for (int i = 0; i < 12; i++) { local[i] = g_deg[base + i]; s += local[i]; }
    int lane = t & 31, w = t >> 5;
    int v = s;
#pragma unroll
    for (int o = 1; o < 32; o <<= 1) {
        int n = __shfl_up_sync(0xffffffffu, v, o);
        if (lane >= o) v += n;
    }
    if (lane == 31) wsum[w] = v;
    __syncthreads();
    if (w == 0) {
        int x = wsum[lane];
#pragma unroll
        for (int o = 1; o < 32; o <<= 1) {
            int n = __shfl_up_sync(0xffffffffu, x, o);
            if (lane >= o) x += n;
        }
        wsum[lane] = x;
    }
    __syncthreads();
    int acc = v - s + (w > 0 ? wsum[w - 1] : 0);   // exclusive prefix
#pragma unroll
    for (int i = 0; i < 12; i++) {
        g_rowptr[base + i] = acc;
        g_fill[base + i]   = acc;
        g_dinv[base + i]   = rsqrtf((float)local[i] + 1.0f);  // +1 self loop
        acc += local[i];
    }
    if (t == 1023) g_rowptr[NN] = acc;
}

__global__ void k_fill(const int* __restrict__ ei) {
    int e = blockIdx.x * blockDim.x + threadIdx.x;
    if (e >= EE) return;
    int s = ei[e], d = ei[EE + e];
    int p = atomicAdd(&g_fill[d], 1);
    g_col[p] = s;
    g_wgt[p] = g_dinv[s] * g_dinv[d];
}

// ---------------- counterfactual rank-1 helpers -------------------------------
__global__ void k_u(const float* __restrict__ x) {
    int i = blockIdx.x * blockDim.x + threadIdx.x;
    if (i < NN) g_u[i] = 1.0f - 2.0f * x[(size_t)i * IND];
}

__global__ void k_agg_scalar() {
    int i = blockIdx.x * blockDim.x + threadIdx.x;
    if (i >= NN) return;
    float di = g_dinv[i];
    float acc = di * di * g_u[i];
    int e = g_rowptr[i + 1];
    for (int p = g_rowptr[i]; p < e; p++) acc += g_wgt[p] * g_u[g_col[p]];
    g_Au[i] = acc;
}

// a1 (gB1) -> h1r=relu(a1) in place ; gB2 = relu(a1 + Au * W1row0)
__global__ void k_rank1relu(const float* __restrict__ W1row0) {
    int i = blockIdx.x, t = threadIdx.x;
    float a = gB1[i * HH + t];
    gB2[i * HH + t] = fmaxf(a + g_Au[i] * W1row0[t], 0.0f);
    gB1[i * HH + t] = fmaxf(a, 0.0f);
}

// ---------------- sparse aggregation: out[i,:] = sum_j A[i,j] in[j, off:off+D]
// 256-thread blocks; 256/D rows per block (feature-parallel, coalesced gathers)
template <int D>
__global__ void __launch_bounds__(256) k_agg(const float* __restrict__ in, int ldi, int off,
                                             const float* __restrict__ bias,
                                             float* __restrict__ outp) {
    constexpr int RPB = 256 / D;
    int i = blockIdx.x * RPB + threadIdx.x / D;
    int t = threadIdx.x % D;
    float di = g_dinv[i];
    float acc = di * di * in[(size_t)i * ldi + off + t];
    int p = g_rowptr[i], e = g_rowptr[i + 1];
    for (; p + 4 <= e; p += 4) {
        int c0 = g_col[p], c1 = g_col[p + 1], c2 = g_col[p + 2], c3 = g_col[p + 3];
        float w0 = g_wgt[p], w1 = g_wgt[p + 1], w2 = g_wgt[p + 2], w3 = g_wgt[p + 3];
        float v0 = in[(size_t)c0 * ldi + off + t];
        float v1 = in[(size_t)c1 * ldi + off + t];
        float v2 = in[(size_t)c2 * ldi + off + t];
        float v3 = in[(size_t)c3 * ldi + off + t];
        acc += w0 * v0 + w1 * v1 + w2 * v2 + w3 * v3;
    }
    for (; p < e; p++) acc += g_wgt[p] * in[(size_t)g_col[p] * ldi + off + t];
    if (bias) acc += bias[t];
    outp[(size_t)i * D + t] = acc;
}

// ---------------- small dense GEMM: out[N x M] = A[N x K] @ W[K x M] (+b)(relu)
template <int K, int M, int R, bool RELU, bool BIAS>
__global__ void k_gemm(const float* __restrict__ A, int lda,
                       const float* __restrict__ W,
                       const float* __restrict__ bias,
                       float* __restrict__ outp, int ldo) {
    __shared__ float sA[R][K];
    int r0 = blockIdx.x * R;
    int tid = threadIdx.x;  // M threads
    for (int idx = tid; idx < R * K; idx += M) {
        int r = idx / K, k = idx % K;
        sA[r][k] = A[(size_t)(r0 + r) * lda + k];
    }
    __syncthreads();
    float acc[R];
#pragma unroll
    for (int r = 0; r < R; r++) acc[r] = BIAS ? bias[tid] : 0.0f;
    for (int k = 0; k < K; k++) {
        float w = __ldg(&W[k * M + tid]);
#pragma unroll
        for (int r = 0; r < R; r++) acc[r] += sA[r][k] * w;
    }
#pragma unroll
    for (int r = 0; r < R; r++) {
        float v = acc[r];
        if (RELU) v = fmaxf(v, 0.0f);
        outp[(size_t)(r0 + r) * ldo + tid] = v;
    }
}

__global__ void k_split(const float* __restrict__ z,
                        float* __restrict__ zs, float* __restrict__ zns) {
    int i = blockIdx.x, t = threadIdx.x;
    float v = z[i * HH + t];
    if (t < 32) zs[i * 32 + t] = v;
    else        zns[i * 32 + (t - 32)] = v;
}

// ---------------- s_ = hs @ hs^T  via TF32 tensor cores (3-pass hi/lo split) --
__device__ __forceinline__ uint32_t f2tf(float f) {
    uint32_t r;
    asm("cvt.rna.tf32.f32 %0, %1;" : "=r"(r) : "f"(f));
    return r;
}
__device__ __forceinline__ void mma8(float* c, uint32_t a0, uint32_t a1, uint32_t a2,
                                     uint32_t a3, uint32_t b0, uint32_t b1) {
    asm volatile(
        "mma.sync.aligned.m16n8k8.row.col.f32.tf32.tf32.f32 "
        "{%0,%1,%2,%3},{%4,%5,%6,%7},{%8,%9},{%0,%1,%2,%3};"
        : "+f"(c[0]), "+f"(c[1]), "+f"(c[2]), "+f"(c[3])
        : "r"(a0), "r"(a1), "r"(a2), "r"(a3), "r"(b0), "r"(b1));
}

#define LDK 68

__global__ void __launch_bounds__(256, 2) k_sgemm_tf32(const float* __restrict__ hs,
                                                       float* __restrict__ outp) {
    extern __shared__ float sm[];
    float* sA = sm;                 // 128 x LDK
    float* sB = sm + 128 * LDK;

    // triangular decode: tb -> (bi >= bj); then use (brow=bj, bcol=bi) upper tri
    int tb = blockIdx.x;
    int bi = (int)((sqrtf(8.0f * (float)tb + 1.0f) - 1.0f) * 0.5f);
    while ((bi + 1) * (bi + 2) / 2 <= tb) ++bi;
    while (bi * (bi + 1) / 2 > tb) --bi;
    int bj = tb - bi * (bi + 1) / 2;
    int brow = bj, bcol = bi;

    int tid = threadIdx.x;
    {
        int r = tid >> 1, half = tid & 1;
        const float* ga = hs + (size_t)(brow * 128 + r) * 64 + half * 32;
        const float* gb = hs + (size_t)(bcol * 128 + r) * 64 + half * 32;
        float* da = sA + r * LDK + half * 32;
        float* db = sB + r * LDK + half * 32;
#pragma unroll
        for (int q = 0; q < 8; q++) {
            ((float4*)da)[q] = ((const float4*)ga)[q];
            ((float4*)db)[q] = ((const float4*)gb)[q];
        }
    }
    __syncthreads();

    int warp = tid >> 5, lane = tid & 31;
    int wm = warp >> 2, wn = warp & 3;       // warp tile: 64 rows x 32 cols
    int grp = lane >> 2, tq = lane & 3;

    float acc[4][4][4];
#pragma unroll
    for (int mt = 0; mt < 4; mt++)
#pragma unroll
        for (int nt = 0; nt < 4; nt++)
#pragma unroll
            for (int q = 0; q < 4; q++) acc[mt][nt][q] = 0.0f;

#pragma unroll
    for (int ks = 0; ks < 8; ks++) {
        int k0 = ks * 8;
        uint32_t bhi[4][2], blo[4][2];
#pragma unroll
        for (int nt = 0; nt < 4; nt++) {
            int n0 = wn * 32 + nt * 8 + grp;
            float b0 = sB[n0 * LDK + k0 + tq];
            float b1 = sB[n0 * LDK + k0 + tq + 4];
            bhi[nt][0] = f2tf(b0);
            blo[nt][0] = f2tf(b0 - __uint_as_float(bhi[nt][0]));
            bhi[nt][1] = f2tf(b1);
            blo[nt][1] = f2tf(b1 - __uint_as_float(bhi[nt][1]));
        }
#pragma unroll
        for (int mt = 0; mt < 4; mt++) {
            int r0 = wm * 64 + mt * 16 + grp;
            float a0 = sA[r0 * LDK + k0 + tq];
            float a1 = sA[(r0 + 8) * LDK + k0 + tq];
            float a2 = sA[r0 * LDK + k0 + tq + 4];
            float a3 = sA[(r0 + 8) * LDK + k0 + tq + 4];
            uint32_t ah0 = f2tf(a0), ah1 = f2tf(a1), ah2 = f2tf(a2), ah3 = f2tf(a3);
            uint32_t al0 = f2tf(a0 - __uint_as_float(ah0));
            uint32_t al1 = f2tf(a1 - __uint_as_float(ah1));
            uint32_t al2 = f2tf(a2 - __uint_as_float(ah2));
            uint32_t al3 = f2tf(a3 - __uint_as_float(ah3));
#pragma unroll
            for (int nt = 0; nt < 4; nt++) {
                mma8(acc[mt][nt], ah0, ah1, ah2, ah3, bhi[nt][0], bhi[nt][1]);
                mma8(acc[mt][nt], al0, al1, al2, al3, bhi[nt][0], bhi[nt][1]);
                mma8(acc[mt][nt], ah0, ah1, ah2, ah3, blo[nt][0], blo[nt][1]);
            }
        }
    }

    // epilogue: direct tile + mirrored tile
#pragma unroll
    for (int mt = 0; mt < 4; mt++) {
        int r0 = brow * 128 + wm * 64 + mt * 16 + grp;
#pragma unroll
        for (int nt = 0; nt < 4; nt++) {
            int c0 = bcol * 128 + wn * 32 + nt * 8 + 2 * tq;
            *(float2*)(outp + (size_t)r0 * NN + c0) =
                make_float2(acc[mt][nt][0], acc[mt][nt][1]);
            *(float2*)(outp + (size_t)(r0 + 8) * NN + c0) =
                make_float2(acc[mt][nt][2], acc[mt][nt][3]);
        }
    }
    if (brow != bcol) {
#pragma unroll
        for (int mt = 0; mt < 4; mt++) {
            int r0 = brow * 128 + wm * 64 + mt * 16 + grp;
#pragma unroll
            for (int nt = 0; nt < 4; nt++) {
                int c0 = bcol * 128 + wn * 32 + nt * 8 + 2 * tq;
                outp[(size_t)c0 * NN + r0]           = acc[mt][nt][0];
                outp[(size_t)(c0 + 1) * NN + r0]     = acc[mt][nt][1];
                outp[(size_t)c0 * NN + r0 + 8]       = acc[mt][nt][2];
                outp[(size_t)(c0 + 1) * NN + r0 + 8] = acc[mt][nt][3];
            }
        }
    }
}

// ---------------- host orchestration -----------------------------------------
extern "C" void kernel_launch(void* const* d_in, const int* in_sizes, int n_in,
                              void* d_out, int out_size) {
    const float* x    = (const float*)d_in[0];
    const int*   ei   = (const int*)d_in[1];
    const float* eW1  = (const float*)d_in[2];
    const float* eb1  = (const float*)d_in[3];
    const float* eW2  = (const float*)d_in[4];
    const float* eb2  = (const float*)d_in[5];
    const float* d1W1 = (const float*)d_in[6];
    const float* d1b1 = (const float*)d_in[7];
    const float* d1W2 = (const float*)d_in[8];
    const float* d1b2 = (const float*)d_in[9];
    const float* d2W1 = (const float*)d_in[10];
    const float* d2b1 = (const float*)d_in[11];
    const float* d2W2 = (const float*)d_in[12];
    const float* d2b2 = (const float*)d_in[13];
    const float* sW   = (const float*)d_in[14];
    const float* sb   = (const float*)d_in[15];

    float* out  = (float*)d_out;
    float* o_zs  = out;
    float* o_zns = out + (size_t)NN * 32;
    float* o_x1  = out + (size_t)NN * 64;
    float* o_x2  = o_x1 + (size_t)NN * 256;
    float* o_x3  = o_x2 + (size_t)NN * 256;
    float* o_s   = o_x3 + (size_t)NN * 256;

    float *B0, *B1, *B2, *B3, *B4, *B5, *B6, *B7;
    cudaGetSymbolAddress((void**)&B0, gB0);
    cudaGetSymbolAddress((void**)&B1, gB1);
    cudaGetSymbolAddress((void**)&B2, gB2);
    cudaGetSymbolAddress((void**)&B3, gB3);
    cudaGetSymbolAddress((void**)&B4, gB4);
    cudaGetSymbolAddress((void**)&B5, gB5);
    cudaGetSymbolAddress((void**)&B6, gB6);
    cudaGetSymbolAddress((void**)&B7, gB7);

    // graph preprocessing (CSR + norms), reused by all aggregations
    k_zero_deg<<<(NN + 255) / 256, 256>>>();
    k_count<<<(EE + 255) / 256, 256>>>(ei);
    k_scan<<<1, 1024>>>();
    k_fill<<<(EE + 255) / 256, 256>>>(ei);
    k_u<<<(NN + 255) / 256, 256>>>(x);
    k_agg_scalar<<<(NN + 255) / 256, 256>>>();

    // encoder layer 1: a1 = A@(x@W1) + b1 ; cf path via rank-1 correction
    k_gemm<256, 64, 8, false, false><<<NN / 8, 64>>>(x, IND, eW1, nullptr, B0, 64);
    k_agg<64><<<NN / 4, 256>>>(B0, 64, 0, eb1, B1);   // B1 = a1
    k_rank1relu<<<NN, 64>>>(eW1);                     // B1 = relu(a1), B2 = relu(a1_cf)

    // encoder layer 2 (both paths): z = A@(h@W2) + b2
    k_gemm<64, 64, 8, false, false><<<NN / 8, 64>>>(B1, 64, eW2, nullptr, B3, 64);
    k_agg<64><<<NN / 4, 256>>>(B3, 64, 0, eb2, B4);   // B4 = z
    k_gemm<64, 64, 8, false, false><<<NN / 8, 64>>>(B2, 64, eW2, nullptr, B3, 64);
    k_agg<64><<<NN / 4, 256>>>(B3, 64, 0, eb2, B5);   // B5 = z_cf

    k_split<<<NN, 64>>>(B4, o_zs, o_zns);

    // merged aggregation: B6 = A@z (both halves, shared by dec1 / hs / dec2)
    k_agg<64><<<NN / 4, 256>>>(B4, 64, 0, nullptr, B6);

    // dec1(z_s): h = relu((A@z_s)@W1 + b) ; x_s_hat = (A@h)@W2 + b
    k_gemm<32, 64, 8, true, true><<<NN / 8, 64>>>(B6, 64, d1W1, d1b1, B7, 64);
    k_agg<64><<<NN / 4, 256>>>(B7, 64, 0, nullptr, B3);
    k_gemm<64, 256, 8, false, true><<<NN / 8, 256>>>(B3, 64, d1W2, d1b2, o_x1, 256);

    // hs = (A@z_ns)@sW + sb
    k_gemm<32, 64, 8, false, true><<<NN / 8, 64>>>(B6 + 32, 64, sW, sb, B0, 64);

    // dec2(z_ns)
    k_gemm<32, 64, 8, true, true><<<NN / 8, 64>>>(B6 + 32, 64, d2W1, d2b1, B7, 64);
    k_agg<64><<<NN / 4, 256>>>(B7, 64, 0, nullptr, B3);
    k_gemm<64, 256, 8, false, true><<<NN / 8, 256>>>(B3, 64, d2W2, d2b2, o_x2, 256);

    // dec1(z_s_cf)
    k_agg<32><<<NN / 8, 256>>>(B5, 64, 0, nullptr, B1);
    k_gemm<32, 64, 8, true, true><<<NN / 8, 64>>>(B1, 32, d1W1, d1b1, B7, 64);
    k_agg<64><<<NN / 4, 256>>>(B7, 64, 0, nullptr, B3);
    k_gemm<64, 256, 8, false, true><<<NN / 8, 256>>>(B3, 64, d1W2, d1b2, o_x3, 256);

    // s_ = hs @ hs^T (symmetric, TF32 tensor cores, triangular grid)
    int smem = 2 * 128 * LDK * (int)sizeof(float);
    cudaFuncSetAttribute(k_sgemm_tf32, cudaFuncAttributeMaxDynamicSharedMemorySize, smem);
    k_sgemm_tf32<<<(96 * 97) / 2, 256, smem>>>(B0, o_s);
}

// round 3
// speedup vs baseline: 1.3125x; 1.0605x over previous
#include <cuda_runtime.h>
#include <cstdint>

#define NN 12288
#define EE 393216
#define IND 256
#define HH 64

// ---------------- scratch (static device globals; no allocation) -------------
__device__ int   g_deg[NN];
__device__ float g_dinv[NN];
__device__ int   g_rowptr[NN + 1];
__device__ int   g_fill[NN];
__device__ int   g_col[EE];
__device__ float g_wgt[EE];
__device__ float g_u[NN];
__device__ float g_Au[NN];
__device__ float gS[(size_t)NN * HH * 9];   // sliced scratch pool

#define UNIT ((size_t)NN * HH)

// ---------------- graph preprocessing ----------------------------------------
__global__ void k_count(const int* __restrict__ ei) {
    int e = blockIdx.x * blockDim.x + threadIdx.x;
    if (e < EE) atomicAdd(&g_deg[ei[EE + e]], 1);
}

// parallel exclusive scan of g_deg -> g_rowptr/g_fill ; also dinv and u
__global__ void k_scan(const float* __restrict__ x) {
    __shared__ int wsum[32];
    int t = threadIdx.x;               // 1024 threads
    int base = t * 12;
    int local[12];
    int s = 0;
#pragma unroll
    for (int i = 0; i < 12; i++) { local[i] = g_deg[base + i]; s += local[i]; }
    int lane = t & 31, w = t >> 5;
    int v = s;
#pragma unroll
    for (int o = 1; o < 32; o <<= 1) {
        int n = __shfl_up_sync(0xffffffffu, v, o);
        if (lane >= o) v += n;
    }
    if (lane == 31) wsum[w] = v;
    __syncthreads();
    if (w == 0) {
        int xx = wsum[lane];
#pragma unroll
        for (int o = 1; o < 32; o <<= 1) {
            int n = __shfl_up_sync(0xffffffffu, xx, o);
            if (lane >= o) xx += n;
        }
        wsum[lane] = xx;
    }
    __syncthreads();
    int acc = v - s + (w > 0 ? wsum[w - 1] : 0);   // exclusive prefix
#pragma unroll
    for (int i = 0; i < 12; i++) {
        g_rowptr[base + i] = acc;
        g_fill[base + i]   = acc;
        g_dinv[base + i]   = rsqrtf((float)local[i] + 1.0f);  // +1 self loop
        g_u[base + i]      = 1.0f - 2.0f * x[(size_t)(base + i) * IND];
        acc += local[i];
    }
    if (t == 1023) g_rowptr[NN] = acc;
}

__global__ void k_fill(const int* __restrict__ ei) {
    int e = blockIdx.x * blockDim.x + threadIdx.x;
    if (e >= EE) return;
    int s = ei[e], d = ei[EE + e];
    int p = atomicAdd(&g_fill[d], 1);
    g_col[p] = s;
    g_wgt[p] = g_dinv[s] * g_dinv[d];
}

__global__ void k_agg_scalar() {
    int i = blockIdx.x * blockDim.x + threadIdx.x;
    if (i >= NN) return;
    float di = g_dinv[i];
    float acc = di * di * g_u[i];
    int e = g_rowptr[i + 1];
    for (int p = g_rowptr[i]; p < e; p++) acc += g_wgt[p] * g_u[g_col[p]];
    g_Au[i] = acc;
}

// ---------------- aggregation gather core -------------------------------------
__device__ __forceinline__ float agg_core(const float* __restrict__ in,
                                          int i, int gi, int t) {
    float di = g_dinv[gi];
    float acc = di * di * in[(size_t)i * HH + t];
    size_t base = (size_t)(i - gi);
    int p = g_rowptr[gi], e = g_rowptr[gi + 1];
    for (; p + 4 <= e; p += 4) {
        int c0 = g_col[p], c1 = g_col[p + 1], c2 = g_col[p + 2], c3 = g_col[p + 3];
        float w0 = g_wgt[p], w1 = g_wgt[p + 1], w2 = g_wgt[p + 2], w3 = g_wgt[p + 3];
        float v0 = in[(base + c0) * HH + t];
        float v1 = in[(base + c1) * HH + t];
        float v2 = in[(base + c2) * HH + t];
        float v3 = in[(base + c3) * HH + t];
        acc += w0 * v0 + w1 * v1 + w2 * v2 + w3 * v3;
    }
    for (; p < e; p++) acc += g_wgt[p] * in[(base + g_col[p]) * HH + t];
    return acc;
}

// plain batched agg over SEG*NN rows (CSR row = i mod NN)
template <int SEG>
__global__ void __launch_bounds__(256) k_aggN(const float* __restrict__ in,
                                              float* __restrict__ outp) {
    int i = blockIdx.x * 4 + threadIdx.x / 64;
    int t = threadIdx.x % 64;
    int gi = i;
    if (SEG >= 2 && gi >= NN) gi -= NN;
    if (SEG >= 3 && gi >= NN) gi -= NN;
    outp[(size_t)i * HH + t] = agg_core(in, i, gi, t);
}

// a1 agg + bias + rank-1 cf + relu: writes [relu(a1); relu(a1_cf)] (2N rows)
__global__ void __launch_bounds__(256) k_agg_a1(const float* __restrict__ in,
                                                const float* __restrict__ b1,
                                                const float* __restrict__ W1row0,
                                                float* __restrict__ outp) {
    int i = blockIdx.x * 4 + threadIdx.x / 64;
    int t = threadIdx.x % 64;
    float a = agg_core(in, i, i, t) + b1[t];
    outp[(size_t)i * HH + t] = fmaxf(a, 0.0f);
    outp[UNIT + (size_t)i * HH + t] = fmaxf(a + g_Au[i] * W1row0[t], 0.0f);
}

// z agg over 2N rows + bias; for first N rows also writes zs/zns outputs
__global__ void __launch_bounds__(256) k_agg_z(const float* __restrict__ in,
                                               const float* __restrict__ b2,
                                               float* __restrict__ outp,
                                               float* __restrict__ zs,
                                               float* __restrict__ zns) {
    int i = blockIdx.x * 4 + threadIdx.x / 64;
    int t = threadIdx.x % 64;
    int gi = (i >= NN) ? i - NN : i;
    float a = agg_core(in, i, gi, t) + b2[t];
    outp[(size_t)i * HH + t] = a;
    if (i < NN) {
        if (t < 32) zs[(size_t)i * 32 + t] = a;
        else        zns[(size_t)i * 32 + (t - 32)] = a;
    }
}

// ---------------- dense GEMM: out[rows x M] = A[rows x K] @ W[K x M] ----------
template <int K, int M, int THREADS, int R, bool RELU, bool BIAS>
__global__ void __launch_bounds__(THREADS) k_gemmT(const float* __restrict__ A, int lda,
                                                   const float* __restrict__ W,
                                                   const float* __restrict__ bias,
                                                   float* __restrict__ outp, int ldo) {
    constexpr int G = THREADS / M;
    constexpr int RG = R / G;
    __shared__ float sA[R][K];
    int r0 = blockIdx.x * R;
    int tid = threadIdx.x;
    int col = tid % M;
    int grp = tid / M;
    for (int idx = tid; idx < R * K; idx += THREADS) {
        int r = idx / K, k = idx - r * K;
        sA[r][k] = A[(size_t)(r0 + r) * lda + k];
    }
    __syncthreads();
    float acc[RG];
#pragma unroll
    for (int r = 0; r < RG; r++) acc[r] = BIAS ? bias[col] : 0.0f;
#pragma unroll 4
    for (int k = 0; k < K; k++) {
        float w = __ldg(&W[k * M + col]);
#pragma unroll
        for (int r = 0; r < RG; r++) acc[r] += sA[grp * RG + r][k] * w;
    }
#pragma unroll
    for (int r = 0; r < RG; r++) {
        float v = RELU ? fmaxf(acc[r], 0.0f) : acc[r];
        outp[(size_t)(r0 + grp * RG + r) * ldo + col] = v;
    }
}

// batched K=32 -> 64 GEMM, 4 configs via blockIdx.y
struct GemmCfg { const float* in; const float* W; const float* bias; float* out; int relu; };

__global__ void __launch_bounds__(256) k_g32x4(GemmCfg c0, GemmCfg c1, GemmCfg c2, GemmCfg c3) {
    GemmCfg c = (blockIdx.y == 0) ? c0 : (blockIdx.y == 1) ? c1 : (blockIdx.y == 2) ? c2 : c3;
    constexpr int K = 32, M = 64, R = 16, RG = 4;
    __shared__ float sA[R][K];
    int r0 = blockIdx.x * R;
    int tid = threadIdx.x;
    int col = tid % M;
    int grp = tid / M;
    for (int idx = tid; idx < R * K; idx += 256) {
        int r = idx / K, k = idx - r * K;
        sA[r][k] = c.in[(size_t)(r0 + r) * 64 + k];
    }
    __syncthreads();
    float acc[RG];
#pragma unroll
    for (int r = 0; r < RG; r++) acc[r] = c.bias[col];
#pragma unroll 4
    for (int k = 0; k < K; k++) {
        float w = __ldg(&c.W[k * M + col]);
#pragma unroll
        for (int r = 0; r < RG; r++) acc[r] += sA[grp * RG + r][k] * w;
    }
#pragma unroll
    for (int r = 0; r < RG; r++) {
        float v = c.relu ? fmaxf(acc[r], 0.0f) : acc[r];
        c.out[(size_t)(r0 + grp * RG + r) * 64 + col] = v;
    }
}

// segmented final GEMM: 3N rows, K=64 -> M=256; seg 0/2 use (W0,b0), seg 1 uses (W1,b1)
__global__ void __launch_bounds__(256) k_g256seg(const float* __restrict__ A,
                                                 const float* __restrict__ W0,
                                                 const float* __restrict__ b0,
                                                 const float* __restrict__ W1,
                                                 const float* __restrict__ b1,
                                                 float* __restrict__ outp) {
    constexpr int K = 64, M = 256, R = 16;
    __shared__ float sA[R][K];
    int r0 = blockIdx.x * R;
    int seg = r0 / NN;
    const float* W = (seg == 1) ? W1 : W0;
    const float* b = (seg == 1) ? b1 : b0;
    int tid = threadIdx.x;
    for (int idx = tid; idx < R * K; idx += 256) {
        int r = idx / K, k = idx - r * K;
        sA[r][k] = A[(size_t)(r0 + r) * K + k];
    }
    __syncthreads();
    float acc[R];
#pragma unroll
    for (int r = 0; r < R; r++) acc[r] = b[tid];
#pragma unroll 4
    for (int k = 0; k < K; k++) {
        float w = __ldg(&W[k * M + tid]);
#pragma unroll
        for (int r = 0; r < R; r++) acc[r] += sA[r][k] * w;
    }
#pragma unroll
    for (int r = 0; r < R; r++)
        outp[(size_t)(r0 + r) * M + tid] = acc[r];
}

// ---------------- s_ = hs @ hs^T  via TF32 tensor cores (3-pass hi/lo split) --
__device__ __forceinline__ uint32_t f2tf(float f) {
    uint32_t r;
    asm("cvt.rna.tf32.f32 %0, %1;" : "=r"(r) : "f"(f));
    return r;
}
__device__ __forceinline__ void mma8(float* c, uint32_t a0, uint32_t a1, uint32_t a2,
                                     uint32_t a3, uint32_t b0, uint32_t b1) {
    asm volatile(
        "mma.sync.aligned.m16n8k8.row.col.f32.tf32.tf32.f32 "
        "{%0,%1,%2,%3},{%4,%5,%6,%7},{%8,%9},{%0,%1,%2,%3};"
        : "+f"(c[0]), "+f"(c[1]), "+f"(c[2]), "+f"(c[3])
        : "r"(a0), "r"(a1), "r"(a2), "r"(a3), "r"(b0), "r"(b1));
}

#define LDK 68

__global__ void __launch_bounds__(256, 2) k_sgemm_tf32(const float* __restrict__ hs,
                                                       float* __restrict__ outp) {
    extern __shared__ float sm[];
    float* sA = sm;                 // 128 x LDK
    float* sB = sm + 128 * LDK;

    int tb = blockIdx.x;
    int bi = (int)((sqrtf(8.0f * (float)tb + 1.0f) - 1.0f) * 0.5f);
    while ((bi + 1) * (bi + 2) / 2 <= tb) ++bi;
    while (bi * (bi + 1) / 2 > tb) --bi;
    int bj = tb - bi * (bi + 1) / 2;
    int brow = bj, bcol = bi;

    int tid = threadIdx.x;
    {
        int r = tid >> 1, half = tid & 1;
        const float* ga = hs + (size_t)(brow * 128 + r) * 64 + half * 32;
        const float* gb = hs + (size_t)(bcol * 128 + r) * 64 + half * 32;
        float* da = sA + r * LDK + half * 32;
        float* db = sB + r * LDK + half * 32;
#pragma unroll
        for (int q = 0; q < 8; q++) {
            ((float4*)da)[q] = ((const float4*)ga)[q];
            ((float4*)db)[q] = ((const float4*)gb)[q];
        }
    }
    __syncthreads();

    int warp = tid >> 5, lane = tid & 31;
    int wm = warp >> 2, wn = warp & 3;       // warp tile: 64 rows x 32 cols
    int grp = lane >> 2, tq = lane & 3;

    float acc[4][4][4];
#pragma unroll
    for (int i = 0; i < 4; i++)
#pragma unroll
        for (int j = 0; j < 4; j++)
#pragma unroll
            for (int q = 0; q < 4; q++) acc[i][j][q] = 0.0f;

#pragma unroll
    for (int ks = 0; ks < 8; ks++) {
        int k0 = ks * 8;
        uint32_t bhi[4][2], blo[4][2];
#pragma unroll
        for (int nt = 0; nt < 4; nt++) {
            int n0 = wn * 32 + nt * 8 + grp;
            float b0 = sB[n0 * LDK + k0 + tq];
            float b1 = sB[n0 * LDK + k0 + tq + 4];
            bhi[nt][0] = f2tf(b0);
            blo[nt][0] = f2tf(b0 - __uint_as_float(bhi[nt][0]));
            bhi[nt][1] = f2tf(b1);
            blo[nt][1] = f2tf(b1 - __uint_as_float(bhi[nt][1]));
        }
#pragma unroll
        for (int mt = 0; mt < 4; mt++) {
            int r0 = wm * 64 + mt * 16 + grp;
            float a0 = sA[r0 * LDK + k0 + tq];
            float a1 = sA[(r0 + 8) * LDK + k0 + tq];
            float a2 = sA[r0 * LDK + k0 + tq + 4];
            float a3 = sA[(r0 + 8) * LDK + k0 + tq + 4];
            uint32_t ah0 = f2tf(a0), ah1 = f2tf(a1), ah2 = f2tf(a2), ah3 = f2tf(a3);
            uint32_t al0 = f2tf(a0 - __uint_as_float(ah0));
            uint32_t al1 = f2tf(a1 - __uint_as_float(ah1));
            uint32_t al2 = f2tf(a2 - __uint_as_float(ah2));
            uint32_t al3 = f2tf(a3 - __uint_as_float(ah3));
#pragma unroll
            for (int nt = 0; nt < 4; nt++) {
                mma8(acc[mt][nt], ah0, ah1, ah2, ah3, bhi[nt][0], bhi[nt][1]);
                mma8(acc[mt][nt], al0, al1, al2, al3, bhi[nt][0], bhi[nt][1]);
                mma8(acc[mt][nt], ah0, ah1, ah2, ah3, blo[nt][0], blo[nt][1]);
            }
        }
    }

#pragma unroll
    for (int mt = 0; mt < 4; mt++) {
        int r0 = brow * 128 + wm * 64 + mt * 16 + grp;
#pragma unroll
        for (int nt = 0; nt < 4; nt++) {
            int c0 = bcol * 128 + wn * 32 + nt * 8 + 2 * tq;
            *(float2*)(outp + (size_t)r0 * NN + c0) =
                make_float2(acc[mt][nt][0], acc[mt][nt][1]);
            *(float2*)(outp + (size_t)(r0 + 8) * NN + c0) =
                make_float2(acc[mt][nt][2], acc[mt][nt][3]);
        }
    }
    if (brow != bcol) {
#pragma unroll
        for (int mt = 0; mt < 4; mt++) {
            int r0 = brow * 128 + wm * 64 + mt * 16 + grp;
#pragma unroll
            for (int nt = 0; nt < 4; nt++) {
                int c0 = bcol * 128 + wn * 32 + nt * 8 + 2 * tq;
                outp[(size_t)c0 * NN + r0]           = acc[mt][nt][0];
                outp[(size_t)(c0 + 1) * NN + r0]     = acc[mt][nt][1];
                outp[(size_t)c0 * NN + r0 + 8]       = acc[mt][nt][2];
                outp[(size_t)(c0 + 1) * NN + r0 + 8] = acc[mt][nt][3];
            }
        }
    }
}

// ---------------- side-stream handles (created once, at static init) ----------
struct SideCtx {
    cudaStream_t side = nullptr;
    cudaEvent_t evF = nullptr, evJ = nullptr;
    SideCtx() {
        if (cudaStreamCreateWithFlags(&side, cudaStreamNonBlocking) != cudaSuccess) { side = nullptr; return; }
        if (cudaEventCreateWithFlags(&evF, cudaEventDisableTiming) != cudaSuccess ||
            cudaEventCreateWithFlags(&evJ, cudaEventDisableTiming) != cudaSuccess) { side = nullptr; }
    }
};
static SideCtx g_ctx;

// ---------------- host orchestration -----------------------------------------
extern "C" void kernel_launch(void* const* d_in, const int* in_sizes, int n_in,
                              void* d_out, int out_size) {
    const float* x    = (const float*)d_in[0];
    const int*   ei   = (const int*)d_in[1];
    const float* eW1  = (const float*)d_in[2];
    const float* eb1  = (const float*)d_in[3];
    const float* eW2  = (const float*)d_in[4];
    const float* eb2  = (const float*)d_in[5];
    const float* d1W1 = (const float*)d_in[6];
    const float* d1b1 = (const float*)d_in[7];
    const float* d1W2 = (const float*)d_in[8];
    const float* d1b2 = (const float*)d_in[9];
    const float* d2W1 = (const float*)d_in[10];
    const float* d2b1 = (const float*)d_in[11];
    const float* d2W2 = (const float*)d_in[12];
    const float* d2b2 = (const float*)d_in[13];
    const float* sW   = (const float*)d_in[14];
    const float* sb   = (const float*)d_in[15];

    float* out  = (float*)d_out;
    float* o_zs  = out;
    float* o_zns = out + (size_t)NN * 32;
    float* o_x1  = out + (size_t)NN * 64;
    float* o_s   = o_x1 + 3 * (size_t)NN * 256;

    float* S;
    cudaGetSymbolAddress((void**)&S, gS);
    float* P0 = S;                 // x@eW1 (N)        / later hs (N)
    float* P1 = S + 1 * UNIT;      // [relu(a1); relu(a1_cf)] (2N)
    float* P2 = S + 3 * UNIT;      // pre-agg z (2N)
    float* P3 = S + 5 * UNIT;      // [z; z_cf] (2N)
    float* P4 = S + 7 * UNIT;      // [A@z; A@z_cf] (2N)... (P4 spans units 7,8)
    float* P6 = S + 1 * UNIT;      // stage-1 relu h (3N)  (reuses P1/P2 space)
    float* P7 = S + 4 * UNIT;      // A@h (3N)             (reuses P2b/P3 space)
    float* HS = S + 8 * UNIT;      // hs (N) -- keep clear of P6/P7 reuse

    // P4 overlaps HS at unit 8! fix: P4 -> units 6? P3 occupies 5,6. Use layout:
    // P0:0  P1:1,2  P2:3,4  P3:5,6  P4:7,8 ... then after P4 consumed by stage-1,
    // P6 -> 1,2,3  P7 -> 4,5,6  HS -> 0 (P0 free after a1 agg).
    HS = P0;

    int* degp; cudaGetSymbolAddress((void**)&degp, g_deg);

    // ---- graph preprocessing ----
    cudaMemsetAsync(degp, 0, NN * sizeof(int));
    k_count<<<(EE + 255) / 256, 256>>>(ei);
    k_scan<<<1, 1024>>>(x);
    k_fill<<<(EE + 255) / 256, 256>>>(ei);
    k_agg_scalar<<<(NN + 255) / 256, 256>>>();

    // ---- encoder ----
    k_gemmT<256, 64, 256, 32, false, false><<<NN / 32, 256>>>(x, IND, eW1, nullptr, P0, 64);
    k_agg_a1<<<NN / 4, 256>>>(P0, eb1, eW1, P1);                 // 2N relu'd h1
    k_gemmT<64, 64, 256, 32, false, false><<<2 * NN / 32, 256>>>(P1, 64, eW2, nullptr, P2, 64);
    k_agg_z<<<2 * NN / 4, 256>>>(P2, eb2, P3, o_zs, o_zns);      // 2N z + split out
    k_aggN<2><<<2 * NN / 4, 256>>>(P3, P4);                      // 2N A@z

    // ---- stage-1 decoder GEMMs + hs (batched) ----
    GemmCfg c0 = { P4,                 d1W1, d1b1, P6,            1 };  // dec1(z_s)
    GemmCfg c1 = { P4 + 32,            d2W1, d2b1, P6 + UNIT,     1 };  // dec2(z_ns)
    GemmCfg c2 = { P4 + UNIT * 64 / 64 * HH * 0, d1W1, d1b1, P6, 1 };   // placeholder fixed below
    c2.in = P4 + (size_t)NN * 64;  c2.W = d1W1; c2.bias = d1b1; c2.out = P6 + 2 * UNIT; c2.relu = 1; // dec1(z_s_cf)
    GemmCfg c3 = { P4 + 32,            sW,   sb,   HS,            0 };  // hs
    dim3 g32(NN / 16, 4);
    k_g32x4<<<g32, 256>>>(c0, c1, c2, c3);

    // ---- fork: s_ = hs @ hs^T on side stream, overlapped with decoder tail ----
    int smem = 2 * 128 * LDK * (int)sizeof(float);
    cudaFuncSetAttribute(k_sgemm_tf32, cudaFuncAttributeMaxDynamicSharedMemorySize, smem);
    bool forked = (g_ctx.side != nullptr);
    if (forked) {
        cudaEventRecord(g_ctx.evF, 0);
        cudaStreamWaitEvent(g_ctx.side, g_ctx.evF, 0);
        k_sgemm_tf32<<<(96 * 97) / 2, 256, smem, g_ctx.side>>>(HS, o_s);
        cudaEventRecord(g_ctx.evJ, g_ctx.side);
    }

    // ---- decoder tail (3N rows batched) ----
    k_aggN<3><<<3 * NN / 4, 256>>>(P6, P7);
    k_g256seg<<<3 * NN / 16, 256>>>(P7, d1W2, d1b2, d2W2, d2b2, o_x1);

    if (forked) {
        cudaStreamWaitEvent(0, g_ctx.evJ, 0);
    } else {
        k_sgemm_tf32<<<(96 * 97) / 2, 256, smem>>>(HS, o_s);
    }
}

// round 5
// speedup vs baseline: 1.4296x; 1.0892x over previous
#include <cuda_runtime.h>
#include <cuda_bf16.h>
#include <cstdint>

#define NN 12288
#define EE 393216
#define IND 256
#define HH 64

// ---------------- scratch (static device globals; no allocation) -------------
__device__ int   g_deg[NN];
__device__ float g_dinv[NN];
__device__ int   g_rowptr[NN + 1];
__device__ int   g_fill[NN];
__device__ int   g_col[EE];
__device__ float g_wgt[EE];
__device__ float g_u[NN];
__device__ float g_Au[NN];
__device__ float gS[(size_t)NN * HH * 9];   // sliced scratch pool

#define UNIT ((size_t)NN * HH)

// ---------------- graph preprocessing ----------------------------------------
__global__ void k_count(const int* __restrict__ ei) {
    int e = blockIdx.x * blockDim.x + threadIdx.x;
    if (e < EE) atomicAdd(&g_deg[ei[EE + e]], 1);
}

// parallel exclusive scan of g_deg -> g_rowptr/g_fill ; also dinv and u
__global__ void k_scan(const float* __restrict__ x) {
    __shared__ int wsum[32];
    int t = threadIdx.x;               // 1024 threads
    int base = t * 12;
    int local[12];
    int s = 0;
#pragma unroll
    for (int i = 0; i < 12; i++) { local[i] = g_deg[base + i]; s += local[i]; }
    int lane = t & 31, w = t >> 5;
    int v = s;
#pragma unroll
    for (int o = 1; o < 32; o <<= 1) {
        int n = __shfl_up_sync(0xffffffffu, v, o);
        if (lane >= o) v += n;
    }
    if (lane == 31) wsum[w] = v;
    __syncthreads();
    if (w == 0) {
        int xx = wsum[lane];
#pragma unroll
        for (int o = 1; o < 32; o <<= 1) {
            int n = __shfl_up_sync(0xffffffffu, xx, o);
            if (lane >= o) xx += n;
        }
        wsum[lane] = xx;
    }
    __syncthreads();
    int acc = v - s + (w > 0 ? wsum[w - 1] : 0);   // exclusive prefix
#pragma unroll
    for (int i = 0; i < 12; i++) {
        g_rowptr[base + i] = acc;
        g_fill[base + i]   = acc;
        g_dinv[base + i]   = rsqrtf((float)local[i] + 1.0f);  // +1 self loop
        g_u[base + i]      = 1.0f - 2.0f * x[(size_t)(base + i) * IND];
        acc += local[i];
    }
    if (t == 1023) g_rowptr[NN] = acc;
}

__global__ void k_fill(const int* __restrict__ ei) {
    int e = blockIdx.x * blockDim.x + threadIdx.x;
    if (e >= EE) return;
    int s = ei[e], d = ei[EE + e];
    int p = atomicAdd(&g_fill[d], 1);
    g_col[p] = s;
    g_wgt[p] = g_dinv[s] * g_dinv[d];
}

// Au = A@u, 4 lanes per row + shuffle reduce
__global__ void __launch_bounds__(256) k_agg_scalar() {
    int idx = blockIdx.x * 256 + threadIdx.x;
    int r = idx >> 2, l = idx & 3;
    if (r >= NN) return;
    float acc = 0.0f;
    if (l == 0) { float di = g_dinv[r]; acc = di * di * g_u[r]; }
    int e = g_rowptr[r + 1];
    for (int p = g_rowptr[r] + l; p < e; p += 4) acc += g_wgt[p] * g_u[g_col[p]];
    acc += __shfl_xor_sync(0xffffffffu, acc, 1);
    acc += __shfl_xor_sync(0xffffffffu, acc, 2);
    if (l == 0) g_Au[r] = acc;
}

// ---------------- aggregation gather core -------------------------------------
__device__ __forceinline__ float agg_core(const float* __restrict__ in,
                                          int i, int gi, int t) {
    float di = g_dinv[gi];
    float acc = di * di * in[(size_t)i * HH + t];
    size_t base = (size_t)(i - gi);
    int p = g_rowptr[gi], e = g_rowptr[gi + 1];
    for (; p + 4 <= e; p += 4) {
        int c0 = g_col[p], c1 = g_col[p + 1], c2 = g_col[p + 2], c3 = g_col[p + 3];
        float w0 = g_wgt[p], w1 = g_wgt[p + 1], w2 = g_wgt[p + 2], w3 = g_wgt[p + 3];
        float v0 = in[(base + c0) * HH + t];
        float v1 = in[(base + c1) * HH + t];
        float v2 = in[(base + c2) * HH + t];
        float v3 = in[(base + c3) * HH + t];
        acc += w0 * v0 + w1 * v1 + w2 * v2 + w3 * v3;
    }
    for (; p < e; p++) acc += g_wgt[p] * in[(base + g_col[p]) * HH + t];
    return acc;
}

// plain batched agg over SEG*NN rows (CSR row = i mod NN)
template <int SEG>
__global__ void __launch_bounds__(256) k_aggN(const float* __restrict__ in,
                                              float* __restrict__ outp) {
    int i = blockIdx.x * 4 + threadIdx.x / 64;
    int t = threadIdx.x % 64;
    int gi = i;
    if (SEG >= 2 && gi >= NN) gi -= NN;
    if (SEG >= 3 && gi >= NN) gi -= NN;
    outp[(size_t)i * HH + t] = agg_core(in, i, gi, t);
}

// a1 agg + bias + rank-1 cf + relu: writes [relu(a1); relu(a1_cf)] (2N rows)
__global__ void __launch_bounds__(256) k_agg_a1(const float* __restrict__ in,
                                                const float* __restrict__ b1,
                                                const float* __restrict__ W1row0,
                                                float* __restrict__ outp) {
    int i = blockIdx.x * 4 + threadIdx.x / 64;
    int t = threadIdx.x % 64;
    float a = agg_core(in, i, i, t) + b1[t];
    outp[(size_t)i * HH + t] = fmaxf(a, 0.0f);
    outp[UNIT + (size_t)i * HH + t] = fmaxf(a + g_Au[i] * W1row0[t], 0.0f);
}

// z agg over 2N rows + bias; for first N rows also writes zs/zns outputs
__global__ void __launch_bounds__(256) k_agg_z(const float* __restrict__ in,
                                               const float* __restrict__ b2,
                                               float* __restrict__ outp,
                                               float* __restrict__ zs,
                                               float* __restrict__ zns) {
    int i = blockIdx.x * 4 + threadIdx.x / 64;
    int t = threadIdx.x % 64;
    int gi = (i >= NN) ? i - NN : i;
    float a = agg_core(in, i, gi, t) + b2[t];
    outp[(size_t)i * HH + t] = a;
    if (i < NN) {
        if (t < 32) zs[(size_t)i * 32 + t] = a;
        else        zns[(size_t)i * 32 + (t - 32)] = a;
    }
}

// ---------------- dense GEMM: out[rows x M] = A[rows x K] @ W[K x M] ----------
template <int K, int M, int THREADS, int R, bool RELU, bool BIAS>
__global__ void __launch_bounds__(THREADS) k_gemmT(const float* __restrict__ A, int lda,
                                                   const float* __restrict__ W,
                                                   const float* __restrict__ bias,
                                                   float* __restrict__ outp, int ldo) {
    constexpr int G = THREADS / M;
    constexpr int RG = R / G;
    __shared__ float sA[R][K];
    int r0 = blockIdx.x * R;
    int tid = threadIdx.x;
    int col = tid % M;
    int grp = tid / M;
    for (int idx = tid; idx < R * K; idx += THREADS) {
        int r = idx / K, k = idx - r * K;
        sA[r][k] = A[(size_t)(r0 + r) * lda + k];
    }
    __syncthreads();
    float acc[RG];
#pragma unroll
    for (int r = 0; r < RG; r++) acc[r] = BIAS ? bias[col] : 0.0f;
#pragma unroll 4
    for (int k = 0; k < K; k++) {
        float w = __ldg(&W[k * M + col]);
#pragma unroll
        for (int r = 0; r < RG; r++) acc[r] += sA[grp * RG + r][k] * w;
    }
#pragma unroll
    for (int r = 0; r < RG; r++) {
        float v = RELU ? fmaxf(acc[r], 0.0f) : acc[r];
        outp[(size_t)(r0 + grp * RG + r) * ldo + col] = v;
    }
}

// batched K=32 -> 64 GEMM, 4 configs via blockIdx.y
struct GemmCfg { const float* in; const float* W; const float* bias; float* out; int relu; };

__global__ void __launch_bounds__(256) k_g32x4(GemmCfg c0, GemmCfg c1, GemmCfg c2, GemmCfg c3) {
    GemmCfg c = (blockIdx.y == 0) ? c0 : (blockIdx.y == 1) ? c1 : (blockIdx.y == 2) ? c2 : c3;
    constexpr int K = 32, M = 64, R = 16, RG = 4;
    __shared__ float sA[R][K];
    int r0 = blockIdx.x * R;
    int tid = threadIdx.x;
    int col = tid % M;
    int grp = tid / M;
    for (int idx = tid; idx < R * K; idx += 256) {
        int r = idx / K, k = idx - r * K;
        sA[r][k] = c.in[(size_t)(r0 + r) * 64 + k];
    }
    __syncthreads();
    float acc[RG];
#pragma unroll
    for (int r = 0; r < RG; r++) acc[r] = c.bias[col];
#pragma unroll 4
    for (int k = 0; k < K; k++) {
        float w = __ldg(&c.W[k * M + col]);
#pragma unroll
        for (int r = 0; r < RG; r++) acc[r] += sA[grp * RG + r][k] * w;
    }
#pragma unroll
    for (int r = 0; r < RG; r++) {
        float v = c.relu ? fmaxf(acc[r], 0.0f) : acc[r];
        c.out[(size_t)(r0 + grp * RG + r) * 64 + col] = v;
    }
}

// segmented final GEMM: 3N rows, K=64 -> M=256; seg 0/2 use (W0,b0), seg 1 uses (W1,b1)
__global__ void __launch_bounds__(256) k_g256seg(const float* __restrict__ A,
                                                 const float* __restrict__ W0,
                                                 const float* __restrict__ b0,
                                                 const float* __restrict__ W1,
                                                 const float* __restrict__ b1,
                                                 float* __restrict__ outp) {
    constexpr int K = 64, M = 256, R = 16;
    __shared__ float sA[R][K];
    int r0 = blockIdx.x * R;
    int seg = r0 / NN;
    const float* W = (seg == 1) ? W1 : W0;
    const float* b = (seg == 1) ? b1 : b0;
    int tid = threadIdx.x;
    for (int idx = tid; idx < R * K; idx += 256) {
        int r = idx / K, k = idx - r * K;
        sA[r][k] = A[(size_t)(r0 + r) * K + k];
    }
    __syncthreads();
    float acc[R];
#pragma unroll
    for (int r = 0; r < R; r++) acc[r] = b[tid];
#pragma unroll 4
    for (int k = 0; k < K; k++) {
        float w = __ldg(&W[k * M + tid]);
#pragma unroll
        for (int r = 0; r < R; r++) acc[r] += sA[r][k] * w;
    }
#pragma unroll
    for (int r = 0; r < R; r++)
        outp[(size_t)(r0 + r) * M + tid] = acc[r];
}

// ---------------- hs -> bf16 hi/lo split (for 3-pass bf16 mma) ----------------
__global__ void __launch_bounds__(256) k_cvt(const float* __restrict__ hs,
                                             __nv_bfloat16* __restrict__ hi,
                                             __nv_bfloat16* __restrict__ lo) {
    int i = blockIdx.x * 256 + threadIdx.x;   // one float4 per thread
    float4 v = ((const float4*)hs)[i];
    __nv_bfloat16 h0 = __float2bfloat16(v.x), h1 = __float2bfloat16(v.y);
    __nv_bfloat16 h2 = __float2bfloat16(v.z), h3 = __float2bfloat16(v.w);
    __nv_bfloat16 l0 = __float2bfloat16(v.x - __bfloat162float(h0));
    __nv_bfloat16 l1 = __float2bfloat16(v.y - __bfloat162float(h1));
    __nv_bfloat16 l2 = __float2bfloat16(v.z - __bfloat162float(h2));
    __nv_bfloat16 l3 = __float2bfloat16(v.w - __bfloat162float(h3));
    ((__nv_bfloat162*)hi)[2 * i]     = __nv_bfloat162(h0, h1);
    ((__nv_bfloat162*)hi)[2 * i + 1] = __nv_bfloat162(h2, h3);
    ((__nv_bfloat162*)lo)[2 * i]     = __nv_bfloat162(l0, l1);
    ((__nv_bfloat162*)lo)[2 * i + 1] = __nv_bfloat162(l2, l3);
}

// ---------------- s_ = hs @ hs^T  via bf16 tensor cores (3-pass hi/lo) --------
__device__ __forceinline__ void mma16(float* c, uint32_t a0, uint32_t a1, uint32_t a2,
                                      uint32_t a3, uint32_t b0, uint32_t b1) {
    asm volatile(
        "mma.sync.aligned.m16n8k16.row.col.f32.bf16.bf16.f32 "
        "{%0,%1,%2,%3},{%4,%5,%6,%7},{%8,%9},{%0,%1,%2,%3};"
        : "+f"(c[0]), "+f"(c[1]), "+f"(c[2]), "+f"(c[3])
        : "r"(a0), "r"(a1), "r"(a2), "r"(a3), "r"(b0), "r"(b1));
}

#define LDP 36   // row stride in u32 (32 pairs + pad); bank = (4*row + col)%32

// permuted pair index: within each 8-pair chunk, pair j -> (j<4) ? 2j : 2(j-4)+1
// so that frag regs (pair t, pair t+4) sit adjacent for one LDS.64
__device__ __forceinline__ int permp(int p) {
    int j = p & 7;
    return (p & ~7) | ((j < 4) ? (2 * j) : (2 * (j - 4) + 1));
}

__global__ void __launch_bounds__(256) k_sgemm_bf16(const __nv_bfloat16* __restrict__ hi,
                                                    const __nv_bfloat16* __restrict__ lo,
                                                    float* __restrict__ outp) {
    extern __shared__ uint32_t smu[];
    uint32_t* sAh = smu;
    uint32_t* sAl = smu + 128 * LDP;
    uint32_t* sBh = smu + 2 * 128 * LDP;
    uint32_t* sBl = smu + 3 * 128 * LDP;

    int tb = blockIdx.x;
    int bi = (int)((sqrtf(8.0f * (float)tb + 1.0f) - 1.0f) * 0.5f);
    while ((bi + 1) * (bi + 2) / 2 <= tb) ++bi;
    while (bi * (bi + 1) / 2 > tb) --bi;
    int bj = tb - bi * (bi + 1) / 2;
    int brow = bj, bcol = bi;

    int tid = threadIdx.x;
    // cooperative load: each thread handles half a row (16 pairs) for all 4 arrays
    {
        int r = tid >> 1, half = tid & 1;
        const uint32_t* srcAh = (const uint32_t*)hi + (size_t)(brow * 128 + r) * 32 + half * 16;
        const uint32_t* srcAl = (const uint32_t*)lo + (size_t)(brow * 128 + r) * 32 + half * 16;
        const uint32_t* srcBh = (const uint32_t*)hi + (size_t)(bcol * 128 + r) * 32 + half * 16;
        const uint32_t* srcBl = (const uint32_t*)lo + (size_t)(bcol * 128 + r) * 32 + half * 16;
        uint32_t* dAh = sAh + r * LDP;
        uint32_t* dAl = sAl + r * LDP;
        uint32_t* dBh = sBh + r * LDP;
        uint32_t* dBl = sBl + r * LDP;
        uint4 qa[4], qb[4], qc[4], qd[4];
#pragma unroll
        for (int q = 0; q < 4; q++) {
            qa[q] = ((const uint4*)srcAh)[q];
            qb[q] = ((const uint4*)srcAl)[q];
            qc[q] = ((const uint4*)srcBh)[q];
            qd[q] = ((const uint4*)srcBl)[q];
        }
#pragma unroll
        for (int i = 0; i < 16; i++) {
            int p = half * 16 + i;
            int np = permp(p);
            uint32_t va = ((const uint32_t*)qa)[i];
            uint32_t vb = ((const uint32_t*)qb)[i];
            uint32_t vc = ((const uint32_t*)qc)[i];
            uint32_t vd = ((const uint32_t*)qd)[i];
            dAh[np] = va; dAl[np] = vb; dBh[np] = vc; dBl[np] = vd;
        }
    }
    __syncthreads();

    int warp = tid >> 5, lane = tid & 31;
    int wm = warp >> 2, wn = warp & 3;       // warp tile: 64 rows x 32 cols
    int grp = lane >> 2, tq = lane & 3;

    float acc[4][4][4];
#pragma unroll
    for (int i = 0; i < 4; i++)
#pragma unroll
        for (int j = 0; j < 4; j++)
#pragma unroll
            for (int q = 0; q < 4; q++) acc[i][j][q] = 0.0f;

#pragma unroll
    for (int ks = 0; ks < 4; ks++) {
        int off = ks * 8 + 2 * tq;
        uint2 bh[4], bl[4];
#pragma unroll
        for (int nt = 0; nt < 4; nt++) {
            int n0 = wn * 32 + nt * 8 + grp;
            bh[nt] = *(const uint2*)(sBh + n0 * LDP + off);
            bl[nt] = *(const uint2*)(sBl + n0 * LDP + off);
        }
#pragma unroll
        for (int mt = 0; mt < 4; mt++) {
            int r0 = wm * 64 + mt * 16 + grp;
            uint2 ah02 = *(const uint2*)(sAh + r0 * LDP + off);
            uint2 ah13 = *(const uint2*)(sAh + (r0 + 8) * LDP + off);
            uint2 al02 = *(const uint2*)(sAl + r0 * LDP + off);
            uint2 al13 = *(const uint2*)(sAl + (r0 + 8) * LDP + off);
#pragma unroll
            for (int nt = 0; nt < 4; nt++) {
                mma16(acc[mt][nt], ah02.x, ah13.x, ah02.y, ah13.y, bh[nt].x, bh[nt].y);
                mma16(acc[mt][nt], ah02.x, ah13.x, ah02.y, ah13.y, bl[nt].x, bl[nt].y);
                mma16(acc[mt][nt], al02.x, al13.x, al02.y, al13.y, bh[nt].x, bh[nt].y);
            }
        }
    }

#pragma unroll
    for (int mt = 0; mt < 4; mt++) {
        int r0 = brow * 128 + wm * 64 + mt * 16 + grp;
#pragma unroll
        for (int nt = 0; nt < 4; nt++) {
            int c0 = bcol * 128 + wn * 32 + nt * 8 + 2 * tq;
            *(float2*)(outp + (size_t)r0 * NN + c0) =
                make_float2(acc[mt][nt][0], acc[mt][nt][1]);
            *(float2*)(outp + (size_t)(r0 + 8) * NN + c0) =
                make_float2(acc[mt][nt][2], acc[mt][nt][3]);
        }
    }
    if (brow != bcol) {
#pragma unroll
        for (int mt = 0; mt < 4; mt++) {
            int r0 = brow * 128 + wm * 64 + mt * 16 + grp;
#pragma unroll
            for (int nt = 0; nt < 4; nt++) {
                int c0 = bcol * 128 + wn * 32 + nt * 8 + 2 * tq;
                outp[(size_t)c0 * NN + r0]           = acc[mt][nt][0];
                outp[(size_t)(c0 + 1) * NN + r0]     = acc[mt][nt][1];
                outp[(size_t)c0 * NN + r0 + 8]       = acc[mt][nt][2];
                outp[(size_t)(c0 + 1) * NN + r0 + 8] = acc[mt][nt][3];
            }
        }
    }
}

// ---------------- side-stream handles (created once, at static init) ----------
struct SideCtx {
    cudaStream_t side = nullptr;
    cudaEvent_t evF = nullptr, evJ = nullptr, evF2 = nullptr, evJ2 = nullptr;
    SideCtx() {
        if (cudaStreamCreateWithFlags(&side, cudaStreamNonBlocking) != cudaSuccess) { side = nullptr; return; }
        if (cudaEventCreateWithFlags(&evF, cudaEventDisableTiming) != cudaSuccess ||
            cudaEventCreateWithFlags(&evJ, cudaEventDisableTiming) != cudaSuccess ||
            cudaEventCreateWithFlags(&evF2, cudaEventDisableTiming) != cudaSuccess ||
            cudaEventCreateWithFlags(&evJ2, cudaEventDisableTiming) != cudaSuccess) { side = nullptr; }
    }
};
static SideCtx g_ctx;

// ---------------- host orchestration -----------------------------------------
extern "C" void kernel_launch(void* const* d_in, const int* in_sizes, int n_in,
                              void* d_out, int out_size) {
    const float* x    = (const float*)d_in[0];
    const int*   ei   = (const int*)d_in[1];
    const float* eW1  = (const float*)d_in[2];
    const float* eb1  = (const float*)d_in[3];
    const float* eW2  = (const float*)d_in[4];
    const float* eb2  = (const float*)d_in[5];
    const float* d1W1 = (const float*)d_in[6];
    const float* d1b1 = (const float*)d_in[7];
    const float* d1W2 = (const float*)d_in[8];
    const float* d1b2 = (const float*)d_in[9];
    const float* d2W1 = (const float*)d_in[10];
    const float* d2b1 = (const float*)d_in[11];
    const float* d2W2 = (const float*)d_in[12];
    const float* d2b2 = (const float*)d_in[13];
    const float* sW   = (const float*)d_in[14];
    const float* sb   = (const float*)d_in[15];

    float* out  = (float*)d_out;
    float* o_zs  = out;
    float* o_zns = out + (size_t)NN * 32;
    float* o_x1  = out + (size_t)NN * 64;
    float* o_s   = o_x1 + 3 * (size_t)NN * 256;

    float* S;
    cudaGetSymbolAddress((void**)&S, gS);
    // layout: P0:0  P1:1,2  P2:3,4  P3:5,6  P4:7,8
    // after P4 consumed: P6:1,2,3  P7:4,5,6  HS:0  bf16 hi/lo: unit 7
    float* P0 = S;
    float* P1 = S + 1 * UNIT;
    float* P2 = S + 3 * UNIT;
    float* P3 = S + 5 * UNIT;
    float* P4 = S + 7 * UNIT;
    float* P6 = S + 1 * UNIT;
    float* P7 = S + 4 * UNIT;
    float* HS = P0;
    __nv_bfloat16* HShi = (__nv_bfloat16*)(S + 7 * UNIT);
    __nv_bfloat16* HSlo = HShi + UNIT;    // UNIT bf16 elems = half a unit of floats

    int* degp; cudaGetSymbolAddress((void**)&degp, g_deg);

    bool forked = (g_ctx.side != nullptr);

    // ---- fork 1: enc1 GEMM (x@eW1) is independent of the CSR build ----
    if (forked) {
        cudaEventRecord(g_ctx.evF2, 0);
        cudaStreamWaitEvent(g_ctx.side, g_ctx.evF2, 0);
        k_gemmT<256, 64, 256, 32, false, false><<<NN / 32, 256, 0, g_ctx.side>>>(
            x, IND, eW1, nullptr, P0, 64);
        cudaEventRecord(g_ctx.evJ2, g_ctx.side);
    }

    // ---- graph preprocessing (main stream) ----
    cudaMemsetAsync(degp, 0, NN * sizeof(int));
    k_count<<<(EE + 255) / 256, 256>>>(ei);
    k_scan<<<1, 1024>>>(x);
    k_fill<<<(EE + 255) / 256, 256>>>(ei);
    k_agg_scalar<<<NN * 4 / 256, 256>>>();

    if (forked) {
        cudaStreamWaitEvent(0, g_ctx.evJ2, 0);
    } else {
        k_gemmT<256, 64, 256, 32, false, false><<<NN / 32, 256>>>(x, IND, eW1, nullptr, P0, 64);
    }

    // ---- encoder ----
    k_agg_a1<<<NN / 4, 256>>>(P0, eb1, eW1, P1);                 // 2N relu'd h1
    k_gemmT<64, 64, 256, 32, false, false><<<2 * NN / 32, 256>>>(P1, 64, eW2, nullptr, P2, 64);
    k_agg_z<<<2 * NN / 4, 256>>>(P2, eb2, P3, o_zs, o_zns);      // 2N z + split out
    k_aggN<2><<<2 * NN / 4, 256>>>(P3, P4);                      // 2N A@z

    // ---- stage-1 decoder GEMMs + hs (batched) ----
    GemmCfg c0 = { P4,                    d1W1, d1b1, P6,            1 };  // dec1(z_s)
    GemmCfg c1 = { P4 + 32,               d2W1, d2b1, P6 + UNIT,     1 };  // dec2(z_ns)
    GemmCfg c2 = { P4 + (size_t)NN * 64,  d1W1, d1b1, P6 + 2 * UNIT, 1 };  // dec1(z_s_cf)
    GemmCfg c3 = { P4 + 32,               sW,   sb,   HS,            0 };  // hs
    dim3 g32(NN / 16, 4);
    k_g32x4<<<g32, 256>>>(c0, c1, c2, c3);

    // hs -> bf16 hi/lo (overwrites P4 space, now dead)
    k_cvt<<<(NN * HH / 4) / 256, 256>>>(HS, HShi, HSlo);

    // ---- fork 2: s_ = hs @ hs^T on side stream, overlapped with decoder tail --
    int smem = 4 * 128 * LDP * (int)sizeof(uint32_t);
    cudaFuncSetAttribute(k_sgemm_bf16, cudaFuncAttributeMaxDynamicSharedMemorySize, smem);
    if (forked) {
        cudaEventRecord(g_ctx.evF, 0);
        cudaStreamWaitEvent(g_ctx.side, g_ctx.evF, 0);
        k_sgemm_bf16<<<(96 * 97) / 2, 256, smem, g_ctx.side>>>(HShi, HSlo, o_s);
        cudaEventRecord(g_ctx.evJ, g_ctx.side);
    }

    // ---- decoder tail (3N rows batched) ----
    k_aggN<3><<<3 * NN / 4, 256>>>(P6, P7);
    k_g256seg<<<3 * NN / 16, 256>>>(P7, d1W2, d1b2, d2W2, d2b2, o_x1);

    if (forked) {
        cudaStreamWaitEvent(0, g_ctx.evJ, 0);
    } else {
        k_sgemm_bf16<<<(96 * 97) / 2, 256, smem>>>(HShi, HSlo, o_s);
    }
}

// round 6
// speedup vs baseline: 1.4357x; 1.0043x over previous
#include <cuda_runtime.h>
#include <cuda_bf16.h>
#include <cstdint>

#define NN 12288
#define EE 393216
#define IND 256
#define HH 64

// ---------------- scratch (static device globals; no allocation) -------------
__device__ int   g_deg[NN];
__device__ float g_dinv[NN];
__device__ int   g_rowptr[NN + 1];
__device__ int   g_fill[NN];
__device__ int   g_col[EE];
__device__ float g_wgt[EE];
__device__ float g_u[NN];
__device__ float g_Au[NN];
__device__ float gS[(size_t)NN * HH * 9];   // sliced scratch pool

#define UNIT ((size_t)NN * HH)
#define HUNIT ((size_t)NN * 32)

// ---------------- graph preprocessing ----------------------------------------
__global__ void k_count(const int* __restrict__ ei) {
    int e = blockIdx.x * blockDim.x + threadIdx.x;
    if (e < EE) atomicAdd(&g_deg[ei[EE + e]], 1);
}

// parallel exclusive scan of g_deg -> g_rowptr/g_fill ; also dinv and u
__global__ void k_scan(const float* __restrict__ x) {
    __shared__ int wsum[32];
    int t = threadIdx.x;               // 1024 threads
    int base = t * 12;
    int local[12];
    int s = 0;
#pragma unroll
    for (int i = 0; i < 12; i++) { local[i] = g_deg[base + i]; s += local[i]; }
    int lane = t & 31, w = t >> 5;
    int v = s;
#pragma unroll
    for (int o = 1; o < 32; o <<= 1) {
        int n = __shfl_up_sync(0xffffffffu, v, o);
        if (lane >= o) v += n;
    }
    if (lane == 31) wsum[w] = v;
    __syncthreads();
    if (w == 0) {
        int xx = wsum[lane];
#pragma unroll
        for (int o = 1; o < 32; o <<= 1) {
            int n = __shfl_up_sync(0xffffffffu, xx, o);
            if (lane >= o) xx += n;
        }
        wsum[lane] = xx;
    }
    __syncthreads();
    int acc = v - s + (w > 0 ? wsum[w - 1] : 0);
#pragma unroll
    for (int i = 0; i < 12; i++) {
        g_rowptr[base + i] = acc;
        g_fill[base + i]   = acc;
        g_dinv[base + i]   = rsqrtf((float)local[i] + 1.0f);  // +1 self loop
        g_u[base + i]      = 1.0f - 2.0f * x[(size_t)(base + i) * IND];
        acc += local[i];
    }
    if (t == 1023) g_rowptr[NN] = acc;
}

__global__ void k_fill(const int* __restrict__ ei) {
    int e = blockIdx.x * blockDim.x + threadIdx.x;
    if (e >= EE) return;
    int s = ei[e], d = ei[EE + e];
    int p = atomicAdd(&g_fill[d], 1);
    g_col[p] = s;
    g_wgt[p] = g_dinv[s] * g_dinv[d];
}

// Au = A@u, 4 lanes per row + shuffle reduce
__global__ void __launch_bounds__(256) k_agg_scalar() {
    int idx = blockIdx.x * 256 + threadIdx.x;
    int r = idx >> 2, l = idx & 3;
    if (r >= NN) return;
    float acc = 0.0f;
    if (l == 0) { float di = g_dinv[r]; acc = di * di * g_u[r]; }
    int e = g_rowptr[r + 1];
    for (int p = g_rowptr[r] + l; p < e; p += 4) acc += g_wgt[p] * g_u[g_col[p]];
    acc += __shfl_xor_sync(0xffffffffu, acc, 1);
    acc += __shfl_xor_sync(0xffffffffu, acc, 2);
    if (l == 0) g_Au[r] = acc;
}

// ---------------- aggregation gather core (parametric ld) ---------------------
__device__ __forceinline__ float agg_core(const float* __restrict__ in, int ldi,
                                          int i, int gi, int t) {
    float di = g_dinv[gi];
    float acc = di * di * in[(size_t)i * ldi + t];
    size_t base = (size_t)(i - gi);
    int p = g_rowptr[gi], e = g_rowptr[gi + 1];
    for (; p + 4 <= e; p += 4) {
        int c0 = g_col[p], c1 = g_col[p + 1], c2 = g_col[p + 2], c3 = g_col[p + 3];
        float w0 = g_wgt[p], w1 = g_wgt[p + 1], w2 = g_wgt[p + 2], w3 = g_wgt[p + 3];
        float v0 = in[(base + c0) * ldi + t];
        float v1 = in[(base + c1) * ldi + t];
        float v2 = in[(base + c2) * ldi + t];
        float v3 = in[(base + c3) * ldi + t];
        acc += w0 * v0 + w1 * v1 + w2 * v2 + w3 * v3;
    }
    for (; p < e; p++) acc += g_wgt[p] * in[(base + g_col[p]) * ldi + t];
    return acc;
}

// plain batched agg over SEG*NN rows, 64 cols (CSR row = i mod NN)
template <int SEG>
__global__ void __launch_bounds__(256) k_aggN(const float* __restrict__ in,
                                              float* __restrict__ outp) {
    int i = blockIdx.x * 4 + threadIdx.x / 64;
    int t = threadIdx.x % 64;
    int gi = i;
    if (SEG >= 2 && gi >= NN) gi -= NN;
    if (SEG >= 3 && gi >= NN) gi -= NN;
    outp[(size_t)i * HH + t] = agg_core(in, HH, i, gi, t);
}

// 32-col agg over N rows: out[i, t] = (A @ in[:, off:off+32])[i, t] (+ bias)
__global__ void __launch_bounds__(256) k_agg32(const float* __restrict__ in, int ldi, int off,
                                               const float* __restrict__ bias,
                                               float* __restrict__ outp) {
    int i = blockIdx.x * 8 + threadIdx.x / 32;
    int t = threadIdx.x % 32;
    float a = agg_core(in + off, ldi, i, i, t);
    if (bias) a += bias[t];
    outp[(size_t)i * 32 + t] = a;
}

// a1 agg + bias + rank-1 cf + relu: writes [relu(a1); relu(a1_cf)] (2 arrays)
__global__ void __launch_bounds__(256) k_agg_a1(const float* __restrict__ in,
                                                const float* __restrict__ b1,
                                                const float* __restrict__ W1row0,
                                                float* __restrict__ h1,
                                                float* __restrict__ h1cf) {
    int i = blockIdx.x * 4 + threadIdx.x / 64;
    int t = threadIdx.x % 64;
    float a = agg_core(in, HH, i, i, t) + b1[t];
    h1[(size_t)i * HH + t] = fmaxf(a, 0.0f);
    h1cf[(size_t)i * HH + t] = fmaxf(a + g_Au[i] * W1row0[t], 0.0f);
}

// z agg over N rows + bias; also writes zs/zns split outputs
__global__ void __launch_bounds__(256) k_agg_z(const float* __restrict__ in,
                                               const float* __restrict__ b2,
                                               float* __restrict__ outp,
                                               float* __restrict__ zs,
                                               float* __restrict__ zns) {
    int i = blockIdx.x * 4 + threadIdx.x / 64;
    int t = threadIdx.x % 64;
    float a = agg_core(in, HH, i, i, t) + b2[t];
    outp[(size_t)i * HH + t] = a;
    if (t < 32) zs[(size_t)i * 32 + t] = a;
    else        zns[(size_t)i * 32 + (t - 32)] = a;
}

// ---------------- dense GEMM: out[rows x M] = A[rows x K] @ W[K x M] ----------
template <int K, int M, int THREADS, int R, bool RELU, bool BIAS>
__global__ void __launch_bounds__(THREADS) k_gemmT(const float* __restrict__ A, int lda,
                                                   const float* __restrict__ W, int ldw,
                                                   const float* __restrict__ bias,
                                                   float* __restrict__ outp, int ldo) {
    constexpr int G = THREADS / M;
    constexpr int RG = R / G;
    __shared__ float sA[R][K];
    int r0 = blockIdx.x * R;
    int tid = threadIdx.x;
    int col = tid % M;
    int grp = tid / M;
    for (int idx = tid; idx < R * K; idx += THREADS) {
        int r = idx / K, k = idx - r * K;
        sA[r][k] = A[(size_t)(r0 + r) * lda + k];
    }
    __syncthreads();
    float acc[RG];
#pragma unroll
    for (int r = 0; r < RG; r++) acc[r] = BIAS ? bias[col] : 0.0f;
#pragma unroll 4
    for (int k = 0; k < K; k++) {
        float w = __ldg(&W[k * ldw + col]);
#pragma unroll
        for (int r = 0; r < RG; r++) acc[r] += sA[grp * RG + r][k] * w;
    }
#pragma unroll
    for (int r = 0; r < RG; r++) {
        float v = RELU ? fmaxf(acc[r], 0.0f) : acc[r];
        outp[(size_t)(r0 + grp * RG + r) * ldo + col] = v;
    }
}

// batched K=32 -> 64 GEMM, up to 3 configs via blockIdx.y ; inputs ld = 32
struct GemmCfg { const float* in; const float* W; const float* bias; float* out; int relu; };

__global__ void __launch_bounds__(256) k_g32x3(GemmCfg c0, GemmCfg c1, GemmCfg c2) {
    GemmCfg c = (blockIdx.y == 0) ? c0 : (blockIdx.y == 1) ? c1 : c2;
    constexpr int K = 32, M = 64, R = 16, RG = 4;
    __shared__ float sA[R][K];
    int r0 = blockIdx.x * R;
    int tid = threadIdx.x;
    int col = tid % M;
    int grp = tid / M;
    for (int idx = tid; idx < R * K; idx += 256) {
        int r = idx / K, k = idx - r * K;
        sA[r][k] = c.in[(size_t)(r0 + r) * 32 + k];
    }
    __syncthreads();
    float acc[RG];
#pragma unroll
    for (int r = 0; r < RG; r++) acc[r] = c.bias[col];
#pragma unroll 4
    for (int k = 0; k < K; k++) {
        float w = __ldg(&c.W[k * M + col]);
#pragma unroll
        for (int r = 0; r < RG; r++) acc[r] += sA[grp * RG + r][k] * w;
    }
#pragma unroll
    for (int r = 0; r < RG; r++) {
        float v = c.relu ? fmaxf(acc[r], 0.0f) : acc[r];
        c.out[(size_t)(r0 + grp * RG + r) * 64 + col] = v;
    }
}

// segmented final GEMM: 3N rows, K=64 -> M=256; seg 0/2 use (W0,b0), seg 1 uses (W1,b1)
__global__ void __launch_bounds__(256) k_g256seg(const float* __restrict__ A,
                                                 const float* __restrict__ W0,
                                                 const float* __restrict__ b0,
                                                 const float* __restrict__ W1,
                                                 const float* __restrict__ b1,
                                                 float* __restrict__ outp) {
    constexpr int K = 64, M = 256, R = 16;
    __shared__ float sA[R][K];
    int r0 = blockIdx.x * R;
    int seg = r0 / NN;
    const float* W = (seg == 1) ? W1 : W0;
    const float* b = (seg == 1) ? b1 : b0;
    int tid = threadIdx.x;
    for (int idx = tid; idx < R * K; idx += 256) {
        int r = idx / K, k = idx - r * K;
        sA[r][k] = A[(size_t)(r0 + r) * K + k];
    }
    __syncthreads();
    float acc[R];
#pragma unroll
    for (int r = 0; r < R; r++) acc[r] = b[tid];
#pragma unroll 4
    for (int k = 0; k < K; k++) {
        float w = __ldg(&W[k * M + tid]);
#pragma unroll
        for (int r = 0; r < R; r++) acc[r] += sA[r][k] * w;
    }
#pragma unroll
    for (int r = 0; r < R; r++)
        outp[(size_t)(r0 + r) * M + tid] = acc[r];
}

// ---------------- hs -> bf16 hi/lo split (for 3-pass bf16 mma) ----------------
__global__ void __launch_bounds__(256) k_cvt(const float* __restrict__ hs,
                                             __nv_bfloat16* __restrict__ hi,
                                             __nv_bfloat16* __restrict__ lo) {
    int i = blockIdx.x * 256 + threadIdx.x;   // one float4 per thread
    float4 v = ((const float4*)hs)[i];
    __nv_bfloat16 h0 = __float2bfloat16(v.x), h1 = __float2bfloat16(v.y);
    __nv_bfloat16 h2 = __float2bfloat16(v.z), h3 = __float2bfloat16(v.w);
    __nv_bfloat16 l0 = __float2bfloat16(v.x - __bfloat162float(h0));
    __nv_bfloat16 l1 = __float2bfloat16(v.y - __bfloat162float(h1));
    __nv_bfloat16 l2 = __float2bfloat16(v.z - __bfloat162float(h2));
    __nv_bfloat16 l3 = __float2bfloat16(v.w - __bfloat162float(h3));
    ((__nv_bfloat162*)hi)[2 * i]     = __nv_bfloat162(h0, h1);
    ((__nv_bfloat162*)hi)[2 * i + 1] = __nv_bfloat162(h2, h3);
    ((__nv_bfloat162*)lo)[2 * i]     = __nv_bfloat162(l0, l1);
    ((__nv_bfloat162*)lo)[2 * i + 1] = __nv_bfloat162(l2, l3);
}

// ---------------- s_ = hs @ hs^T  via bf16 tensor cores (3-pass hi/lo) --------
__device__ __forceinline__ void mma16(float* c, uint32_t a0, uint32_t a1, uint32_t a2,
                                      uint32_t a3, uint32_t b0, uint32_t b1) {
    asm volatile(
        "mma.sync.aligned.m16n8k16.row.col.f32.bf16.bf16.f32 "
        "{%0,%1,%2,%3},{%4,%5,%6,%7},{%8,%9},{%0,%1,%2,%3};"
        : "+f"(c[0]), "+f"(c[1]), "+f"(c[2]), "+f"(c[3])
        : "r"(a0), "r"(a1), "r"(a2), "r"(a3), "r"(b0), "r"(b1));
}

#define LDP 36

__device__ __forceinline__ int permp(int p) {
    int j = p & 7;
    return (p & ~7) | ((j < 4) ? (2 * j) : (2 * (j - 4) + 1));
}

__global__ void __launch_bounds__(256) k_sgemm_bf16(const __nv_bfloat16* __restrict__ hi,
                                                    const __nv_bfloat16* __restrict__ lo,
                                                    float* __restrict__ outp) {
    extern __shared__ uint32_t smu[];
    uint32_t* sAh = smu;
    uint32_t* sAl = smu + 128 * LDP;
    uint32_t* sBh = smu + 2 * 128 * LDP;
    uint32_t* sBl = smu + 3 * 128 * LDP;

    int tb = blockIdx.x;
    int bi = (int)((sqrtf(8.0f * (float)tb + 1.0f) - 1.0f) * 0.5f);
    while ((bi + 1) * (bi + 2) / 2 <= tb) ++bi;
    while (bi * (bi + 1) / 2 > tb) --bi;
    int bj = tb - bi * (bi + 1) / 2;
    int brow = bj, bcol = bi;

    int tid = threadIdx.x;
    {
        int r = tid >> 1, half = tid & 1;
        const uint32_t* srcAh = (const uint32_t*)hi + (size_t)(brow * 128 + r) * 32 + half * 16;
        const uint32_t* srcAl = (const uint32_t*)lo + (size_t)(brow * 128 + r) * 32 + half * 16;
        const uint32_t* srcBh = (const uint32_t*)hi + (size_t)(bcol * 128 + r) * 32 + half * 16;
        const uint32_t* srcBl = (const uint32_t*)lo + (size_t)(bcol * 128 + r) * 32 + half * 16;
        uint32_t* dAh = sAh + r * LDP;
        uint32_t* dAl = sAl + r * LDP;
        uint32_t* dBh = sBh + r * LDP;
        uint32_t* dBl = sBl + r * LDP;
        uint4 qa[4], qb[4], qc[4], qd[4];
#pragma unroll
        for (int q = 0; q < 4; q++) {
            qa[q] = ((const uint4*)srcAh)[q];
            qb[q] = ((const uint4*)srcAl)[q];
            qc[q] = ((const uint4*)srcBh)[q];
            qd[q] = ((const uint4*)srcBl)[q];
        }
#pragma unroll
        for (int i = 0; i < 16; i++) {
            int p = half * 16 + i;
            int np = permp(p);
            dAh[np] = ((const uint32_t*)qa)[i];
            dAl[np] = ((const uint32_t*)qb)[i];
            dBh[np] = ((const uint32_t*)qc)[i];
            dBl[np] = ((const uint32_t*)qd)[i];
        }
    }
    __syncthreads();

    int warp = tid >> 5, lane = tid & 31;
    int wm = warp >> 2, wn = warp & 3;
    int grp = lane >> 2, tq = lane & 3;

    float acc[4][4][4];
#pragma unroll
    for (int i = 0; i < 4; i++)
#pragma unroll
        for (int j = 0; j < 4; j++)
#pragma unroll
            for (int q = 0; q < 4; q++) acc[i][j][q] = 0.0f;

#pragma unroll
    for (int ks = 0; ks < 4; ks++) {
        int off = ks * 8 + 2 * tq;
        uint2 bh[4], bl[4];
#pragma unroll
        for (int nt = 0; nt < 4; nt++) {
            int n0 = wn * 32 + nt * 8 + grp;
            bh[nt] = *(const uint2*)(sBh + n0 * LDP + off);
            bl[nt] = *(const uint2*)(sBl + n0 * LDP + off);
        }
#pragma unroll
        for (int mt = 0; mt < 4; mt++) {
            int r0 = wm * 64 + mt * 16 + grp;
            uint2 ah02 = *(const uint2*)(sAh + r0 * LDP + off);
            uint2 ah13 = *(const uint2*)(sAh + (r0 + 8) * LDP + off);
            uint2 al02 = *(const uint2*)(sAl + r0 * LDP + off);
            uint2 al13 = *(const uint2*)(sAl + (r0 + 8) * LDP + off);
#pragma unroll
            for (int nt = 0; nt < 4; nt++) {
                mma16(acc[mt][nt], ah02.x, ah13.x, ah02.y, ah13.y, bh[nt].x, bh[nt].y);
                mma16(acc[mt][nt], ah02.x, ah13.x, ah02.y, ah13.y, bl[nt].x, bl[nt].y);
                mma16(acc[mt][nt], al02.x, al13.x, al02.y, al13.y, bh[nt].x, bh[nt].y);
            }
        }
    }

#pragma unroll
    for (int mt = 0; mt < 4; mt++) {
        int r0 = brow * 128 + wm * 64 + mt * 16 + grp;
#pragma unroll
        for (int nt = 0; nt < 4; nt++) {
            int c0 = bcol * 128 + wn * 32 + nt * 8 + 2 * tq;
            __stcs((float2*)(outp + (size_t)r0 * NN + c0),
                   make_float2(acc[mt][nt][0], acc[mt][nt][1]));
            __stcs((float2*)(outp + (size_t)(r0 + 8) * NN + c0),
                   make_float2(acc[mt][nt][2], acc[mt][nt][3]));
        }
    }
    if (brow != bcol) {
#pragma unroll
        for (int mt = 0; mt < 4; mt++) {
            int r0 = brow * 128 + wm * 64 + mt * 16 + grp;
#pragma unroll
            for (int nt = 0; nt < 4; nt++) {
                int c0 = bcol * 128 + wn * 32 + nt * 8 + 2 * tq;
                __stcs(outp + (size_t)c0 * NN + r0,           acc[mt][nt][0]);
                __stcs(outp + (size_t)(c0 + 1) * NN + r0,     acc[mt][nt][1]);
                __stcs(outp + (size_t)c0 * NN + r0 + 8,       acc[mt][nt][2]);
                __stcs(outp + (size_t)(c0 + 1) * NN + r0 + 8, acc[mt][nt][3]);
            }
        }
    }
}

// ---------------- side-stream handles (created once, at static init) ----------
struct SideCtx {
    cudaStream_t side = nullptr;
    cudaEvent_t evF = nullptr, evJ = nullptr, evF2 = nullptr, evJ2 = nullptr;
    SideCtx() {
        if (cudaStreamCreateWithFlags(&side, cudaStreamNonBlocking) != cudaSuccess) { side = nullptr; return; }
        if (cudaEventCreateWithFlags(&evF, cudaEventDisableTiming) != cudaSuccess ||
            cudaEventCreateWithFlags(&evJ, cudaEventDisableTiming) != cudaSuccess ||
            cudaEventCreateWithFlags(&evF2, cudaEventDisableTiming) != cudaSuccess ||
            cudaEventCreateWithFlags(&evJ2, cudaEventDisableTiming) != cudaSuccess) { side = nullptr; }
    }
};
static SideCtx g_ctx;

// ---------------- host orchestration -----------------------------------------
extern "C" void kernel_launch(void* const* d_in, const int* in_sizes, int n_in,
                              void* d_out, int out_size) {
    const float* x    = (const float*)d_in[0];
    const int*   ei   = (const int*)d_in[1];
    const float* eW1  = (const float*)d_in[2];
    const float* eb1  = (const float*)d_in[3];
    const float* eW2  = (const float*)d_in[4];
    const float* eb2  = (const float*)d_in[5];
    const float* d1W1 = (const float*)d_in[6];
    const float* d1b1 = (const float*)d_in[7];
    const float* d1W2 = (const float*)d_in[8];
    const float* d1b2 = (const float*)d_in[9];
    const float* d2W1 = (const float*)d_in[10];
    const float* d2b1 = (const float*)d_in[11];
    const float* d2W2 = (const float*)d_in[12];
    const float* d2b2 = (const float*)d_in[13];
    const float* sW   = (const float*)d_in[14];
    const float* sb   = (const float*)d_in[15];

    float* out  = (float*)d_out;
    float* o_zs  = out;
    float* o_zns = out + (size_t)NN * 32;
    float* o_x1  = out + (size_t)NN * 64;
    float* o_s   = o_x1 + 3 * (size_t)NN * 256;

    float* S;
    cudaGetSymbolAddress((void**)&S, gS);
    // unit layout (UNIT = NN*64 floats):
    // u0: enc1 out -> later P6 seg0     u1: h1 -> later P6 seg1
    // u2: h1cf -> later P6 seg2         u3: P2 (h1@W2) -> ZSCFA -> P7 seg0
    // u4: z (P3) -> P7 seg1             u5: [ZNSA | ZSA] -> P7 seg2
    // u6: HS                            u7: HShi|HSlo (bf16)
    // u8: [P2cf | ZSCF]
    float* U0 = S;
    float* U1 = S + 1 * UNIT;
    float* U2 = S + 2 * UNIT;
    float* U3 = S + 3 * UNIT;
    float* U4 = S + 4 * UNIT;
    float* U5 = S + 5 * UNIT;
    float* U6 = S + 6 * UNIT;
    float* U8 = S + 8 * UNIT;
    float* ZNSA  = U5;
    float* ZSA   = U5 + HUNIT;
    float* P2cf  = U8;
    float* ZSCF  = U8 + HUNIT;
    float* ZSCFA = U3;
    float* HS    = U6;
    __nv_bfloat16* HShi = (__nv_bfloat16*)(S + 7 * UNIT);
    __nv_bfloat16* HSlo = HShi + UNIT;

    int* degp; cudaGetSymbolAddress((void**)&degp, g_deg);
    bool forked = (g_ctx.side != nullptr);

    // ---- fork 1: enc1 GEMM (x@eW1) independent of CSR build ----
    if (forked) {
        cudaEventRecord(g_ctx.evF2, 0);
        cudaStreamWaitEvent(g_ctx.side, g_ctx.evF2, 0);
        k_gemmT<256, 64, 256, 32, false, false><<<NN / 32, 256, 0, g_ctx.side>>>(
            x, IND, eW1, 64, nullptr, U0, 64);
        cudaEventRecord(g_ctx.evJ2, g_ctx.side);
    }

    // ---- graph preprocessing (main stream) ----
    cudaMemsetAsync(degp, 0, NN * sizeof(int));
    k_count<<<(EE + 255) / 256, 256>>>(ei);
    k_scan<<<1, 1024>>>(x);
    k_fill<<<(EE + 255) / 256, 256>>>(ei);
    k_agg_scalar<<<NN * 4 / 256, 256>>>();

    if (forked) cudaStreamWaitEvent(0, g_ctx.evJ2, 0);
    else k_gemmT<256, 64, 256, 32, false, false><<<NN / 32, 256>>>(x, IND, eW1, 64, nullptr, U0, 64);

    // ---- minimal critical path to hs ----
    k_agg_a1<<<NN / 4, 256>>>(U0, eb1, eW1, U1, U2);                          // h1, h1cf
    k_gemmT<64, 64, 256, 32, false, false><<<NN / 32, 256>>>(U1, 64, eW2, 64, nullptr, U3, 64);
    k_agg_z<<<NN / 4, 256>>>(U3, eb2, U4, o_zs, o_zns);                       // z + split out
    k_agg32<<<NN / 8, 256>>>(U4, 64, 32, nullptr, ZNSA);                      // A@z_ns
    {   // hs = ZNSA@sW + sb
        GemmCfg ch = { ZNSA, sW, sb, HS, 0 };
        dim3 g(NN / 16, 1);
        k_g32x3<<<g, 256>>>(ch, ch, ch);
    }
    k_cvt<<<(NN * HH / 4) / 256, 256>>>(HS, HShi, HSlo);

    // ---- fork 2: s_ = hs @ hs^T on side stream ----
    int smem = 4 * 128 * LDP * (int)sizeof(uint32_t);
    cudaFuncSetAttribute(k_sgemm_bf16, cudaFuncAttributeMaxDynamicSharedMemorySize, smem);
    if (forked) {
        cudaEventRecord(g_ctx.evF, 0);
        cudaStreamWaitEvent(g_ctx.side, g_ctx.evF, 0);
        k_sgemm_bf16<<<(96 * 97) / 2, 256, smem, g_ctx.side>>>(HShi, HSlo, o_s);
        cudaEventRecord(g_ctx.evJ, g_ctx.side);
    }

    // ---- cf + decoder pipelines under the sgemm umbrella ----
    // cf: z_s_cf = A@(h1cf @ eW2[:, :32]) + eb2[:32] ; then A@z_s_cf
    k_gemmT<64, 32, 256, 32, false, false><<<NN / 32, 256>>>(U2, 64, eW2, 64, nullptr, P2cf, 32);
    k_agg32<<<NN / 8, 256>>>(P2cf, 32, 0, eb2, ZSCF);
    k_agg32<<<NN / 8, 256>>>(ZSCF, 32, 0, nullptr, ZSCFA);
    k_agg32<<<NN / 8, 256>>>(U4, 64, 0, nullptr, ZSA);                        // A@z_s

    GemmCfg c0 = { ZSA,   d1W1, d1b1, U0, 1 };   // dec1(z_s)
    GemmCfg c1 = { ZNSA,  d2W1, d2b1, U1, 1 };   // dec2(z_ns)
    GemmCfg c2 = { ZSCFA, d1W1, d1b1, U2, 1 };   // dec1(z_s_cf)
    dim3 g32(NN / 16, 3);
    k_g32x3<<<g32, 256>>>(c0, c1, c2);

    k_aggN<3><<<3 * NN / 4, 256>>>(U0, U3);                                   // A@h (3N)
    k_g256seg<<<3 * NN / 16, 256>>>(U3, d1W2, d1b2, d2W2, d2b2, o_x1);

    if (forked) cudaStreamWaitEvent(0, g_ctx.evJ, 0);
    else k_sgemm_bf16<<<(96 * 97) / 2, 256, smem>>>(HShi, HSlo, o_s);
}